// round 2
// baseline (speedup 1.0000x reference)
#include <cuda_runtime.h>
#include <math.h>

// ----------------------------------------------------------------------------
// Device-global constant storage (computed by init kernel each launch).
//   g_C5 : CG tensor for (2,1,1), layout [a(5)][j(3)][k(3)]
//   g_Wk : weights [6][8][8] with the scalar CG coefficient of combos 0..4
//          folded in (combo 5 keeps raw W, uses g_C5).
// ----------------------------------------------------------------------------
__device__ float g_C5[45];
__device__ float g_Wk[384];

// ---------------- complex double helpers (init only) ------------------------
struct cplx { double re, im; };
__device__ __forceinline__ cplx cxmul(cplx a, cplx b) {
    cplx r; r.re = a.re * b.re - a.im * b.im; r.im = a.re * b.im + a.im * b.re; return r;
}

__device__ double d_fact(int n) { double r = 1.0; for (int i = 2; i <= n; i++) r *= i; return r; }

// Racah complex CG coefficient <j1 m1 j2 m2 | j3 m3>
__device__ double d_cgc(int j1, int m1, int j2, int m2, int j3, int m3) {
    if (m3 != m1 + m2) return 0.0;
    int vmin = 0;
    if (j2 - j3 - m1 > vmin) vmin = j2 - j3 - m1;
    if (j1 + m2 - j3 > vmin) vmin = j1 + m2 - j3;
    int vmax = j1 + j2 - j3;
    if (j1 - m1 < vmax) vmax = j1 - m1;
    if (j2 + m2 < vmax) vmax = j2 + m2;
    double pref = (2.0 * j3 + 1.0) * d_fact(j3 + j1 - j2) * d_fact(j3 - j1 + j2)
                * d_fact(j1 + j2 - j3) / d_fact(j1 + j2 + j3 + 1);
    pref *= d_fact(j3 + m3) * d_fact(j3 - m3) * d_fact(j1 - m1) * d_fact(j1 + m1)
          * d_fact(j2 - m2) * d_fact(j2 + m2);
    double s = 0.0;
    for (int v = vmin; v <= vmax; v++) {
        double t = 1.0 / (d_fact(v) * d_fact(j1 + j2 - j3 - v) * d_fact(j1 - m1 - v)
                        * d_fact(j2 + m2 - v) * d_fact(j3 - j2 + m1 + v) * d_fact(j3 - j1 - m2 + v));
        s += (v & 1) ? -t : t;
    }
    return sqrt(pref) * s;
}

// e3nn real->complex change of basis, times (-i)^l
__device__ void d_qmat(int l, cplx q[5][5]) {
    for (int i = 0; i < 5; i++) for (int j = 0; j < 5; j++) { q[i][j].re = 0.0; q[i][j].im = 0.0; }
    const double is2 = 0.70710678118654752440;
    for (int m = -l; m < 0; m++) {
        q[l + m][l - m].re = is2;     // q[l+m, l+|m|]
        q[l + m][l + m].im = -is2;    // q[l+m, l-|m|]
    }
    q[l][l].re = 1.0;
    for (int m = 1; m <= l; m++) {
        double sgn = (m & 1) ? -1.0 : 1.0;
        q[l + m][l + m].re = sgn * is2;
        q[l + m][l - m].im = sgn * is2;
    }
    // multiply all entries by (-i)^l : (a+bi)*(-i) = b - ai
    for (int p = 0; p < l; p++)
        for (int i = 0; i < 5; i++) for (int j = 0; j < 5; j++) {
            double re = q[i][j].re, im = q[i][j].im;
            q[i][j].re = im; q[i][j].im = -re;
        }
}

// real-basis CG, unit Frobenius norm. out layout: [j(d1)][l(d2)][m(d3)] flattened
__device__ void d_so3(int l1, int l2, int l3, float* out) {
    cplx q1[5][5], q2[5][5], q3[5][5];
    d_qmat(l1, q1); d_qmat(l2, q2); d_qmat(l3, q3);
    int d1 = 2 * l1 + 1, d2 = 2 * l2 + 1, d3 = 2 * l3 + 1;
    double C[45];
    double norm = 0.0;
    for (int j = 0; j < d1; j++)
        for (int l = 0; l < d2; l++)
            for (int m = 0; m < d3; m++) {
                double acc = 0.0;
                for (int i = 0; i < d1; i++)
                    for (int k = 0; k < d2; k++) {
                        int n = (i - l1) + (k - l2) + l3;   // m3 = m1 + m2
                        if (n < 0 || n >= d3) continue;
                        double s = d_cgc(l1, i - l1, l2, k - l2, l3, n - l3);
                        if (s == 0.0) continue;
                        cplx t = cxmul(q1[i][j], q2[k][l]);
                        cplx c3; c3.re = q3[n][m].re; c3.im = -q3[n][m].im;
                        t = cxmul(t, c3);
                        acc += t.re * s;
                    }
                C[(j * d2 + l) * d3 + m] = acc;
                norm += acc * acc;
            }
    double inv = 1.0 / sqrt(norm);
    for (int x = 0; x < d1 * d2 * d3; x++) out[x] = (float)(C[x] * inv);
}

__global__ void cg_init_kernel(const float* __restrict__ W) {
    if (threadIdx.x != 0 || blockIdx.x != 0) return;
    float tmp[45];
    float ks[6];
    d_so3(0, 0, 0, tmp); ks[0] = tmp[0];        // scalar
    d_so3(0, 1, 1, tmp); ks[1] = tmp[0];        // k * delta_{lm}
    d_so3(1, 0, 1, tmp); ks[2] = tmp[0];        // k * delta_{jm}
    d_so3(1, 1, 0, tmp); ks[3] = tmp[0];        // k * delta_{jl}
    d_so3(1, 1, 1, tmp); ks[4] = tmp[5];        // k * eps_{jlm}, entry [0][1][2]
    ks[5] = 1.0f;                                // combo 5 generic via g_C5
    d_so3(2, 1, 1, tmp);
    for (int x = 0; x < 45; x++) g_C5[x] = tmp[x];
    for (int c = 0; c < 6; c++)
        for (int x = 0; x < 64; x++)
            g_Wk[c * 64 + x] = W[c * 64 + x] * ks[c];
}

// ----------------------------------------------------------------------------
// Main edge kernel: one thread per edge.
// ----------------------------------------------------------------------------
__global__ __launch_bounds__(256)
void edge_tp_kernel(const float* __restrict__ node,
                    const int*   __restrict__ ei,
                    const float* __restrict__ sh0,
                    const float* __restrict__ sh1,
                    const float* __restrict__ sh2,
                    float*       __restrict__ out,
                    int E) {
    __shared__ float sW[384];        // [6][8][8]
    __shared__ float sC5[45];        // [5][3][3]
    for (int x = threadIdx.x; x < 384; x += blockDim.x) sW[x] = g_Wk[x];
    for (int x = threadIdx.x; x < 45;  x += blockDim.x) sC5[x] = g_C5[x];
    __syncthreads();

    int e = blockIdx.x * blockDim.x + threadIdx.x;
    if (e >= E) return;

    int s = __ldg(ei + e);
    int t = __ldg(ei + E + e);

    // gather source node row (32 floats, 128B-aligned)
    float f[32];
    const float4* row = reinterpret_cast<const float4*>(node + (size_t)s * 32);
    #pragma unroll
    for (int v = 0; v < 8; v++) {
        float4 r = __ldg(row + v);
        f[4 * v + 0] = r.x; f[4 * v + 1] = r.y; f[4 * v + 2] = r.z; f[4 * v + 3] = r.w;
    }

    float h0  = __ldg(sh0 + e);
    float h1x = __ldg(sh1 + 3 * (size_t)e + 0);
    float h1y = __ldg(sh1 + 3 * (size_t)e + 1);
    float h1z = __ldg(sh1 + 3 * (size_t)e + 2);
    float h2[5];
    #pragma unroll
    for (int a = 0; a < 5; a++) h2[a] = __ldg(sh2 + 5 * (size_t)e + a);

    // S5[j][k] = sum_a C5[a][j][k] * sh2[a]   (combo 5 per-edge 3x3 matrix)
    float S5[3][3];
    #pragma unroll
    for (int j = 0; j < 3; j++)
        #pragma unroll
        for (int k = 0; k < 3; k++) {
            float acc = 0.f;
            #pragma unroll
            for (int a = 0; a < 5; a++) acc += sC5[a * 9 + j * 3 + k] * h2[a];
            S5[j][k] = acc;
        }

    float msg[32];
    #pragma unroll
    for (int v = 0; v < 32; v++) msg[v] = 0.f;

    #pragma unroll
    for (int i = 0; i < 8; i++) {
        float f0 = f[i];
        float fx = f[8 + 3 * i], fy = f[9 + 3 * i], fz = f[10 + 3 * i];
        // per-input-channel base quantities (scalar CG norms folded into sW)
        float a  = h0 * f0;                                 // (0,0,0)
        float b  = h1x * fx + h1y * fy + h1z * fz;          // (1,1,0) dot
        float p0 = h0 * fx, p1 = h0 * fy, p2 = h0 * fz;     // (0,1,1)
        float q0 = h1x * f0, q1 = h1y * f0, q2 = h1z * f0;  // (1,0,1)
        float r0 = h1y * fz - h1z * fy;                     // (1,1,1) cross
        float r1 = h1z * fx - h1x * fz;
        float r2 = h1x * fy - h1y * fx;
        float u0 = S5[0][0] * fx + S5[1][0] * fy + S5[2][0] * fz;   // (2,1,1)
        float u1 = S5[0][1] * fx + S5[1][1] * fy + S5[2][1] * fz;
        float u2 = S5[0][2] * fx + S5[1][2] * fy + S5[2][2] * fz;

        #pragma unroll
        for (int o = 0; o < 8; o++) {
            float w0 = sW[0 * 64 + i * 8 + o];
            float w1 = sW[1 * 64 + i * 8 + o];
            float w2 = sW[2 * 64 + i * 8 + o];
            float w3 = sW[3 * 64 + i * 8 + o];
            float w4 = sW[4 * 64 + i * 8 + o];
            float w5 = sW[5 * 64 + i * 8 + o];
            msg[o] += w0 * a + w3 * b;
            msg[8 + 3 * o + 0] += w1 * p0 + w2 * q0 + w4 * r0 + w5 * u0;
            msg[8 + 3 * o + 1] += w1 * p1 + w2 * q1 + w4 * r1 + w5 * u1;
            msg[8 + 3 * o + 2] += w1 * p2 + w2 * q2 + w4 * r2 + w5 * u2;
        }
    }

    // scatter-add: 8x vector float4 reductions (no return) to L2-resident output
    float* orow = out + (size_t)t * 32;
    #pragma unroll
    for (int v = 0; v < 8; v++) {
        asm volatile("red.global.add.v4.f32 [%0], {%1, %2, %3, %4};"
                     :: "l"(orow + 4 * v),
                        "f"(msg[4 * v + 0]), "f"(msg[4 * v + 1]),
                        "f"(msg[4 * v + 2]), "f"(msg[4 * v + 3])
                     : "memory");
    }
}

// ----------------------------------------------------------------------------
// Launch: memset output (poisoned by harness), init constants, run edges.
// Graph-capturable: async memset + kernel launches only, no allocations.
// ----------------------------------------------------------------------------
extern "C" void kernel_launch(void* const* d_in, const int* in_sizes, int n_in,
                              void* d_out, int out_size) {
    const float* node = (const float*)d_in[0];
    const int*   ei   = (const int*)  d_in[1];
    const float* sh0  = (const float*)d_in[2];
    const float* sh1  = (const float*)d_in[3];
    const float* sh2  = (const float*)d_in[4];
    const float* W    = (const float*)d_in[5];
    int E = in_sizes[1] / 2;

    cudaMemsetAsync(d_out, 0, (size_t)out_size * sizeof(float), 0);
    cg_init_kernel<<<1, 1>>>(W);
    int threads = 256;
    int blocks = (E + threads - 1) / threads;
    edge_tp_kernel<<<blocks, threads>>>(node, ei, sh0, sh1, sh2, (float*)d_out, E);
}

// round 3
// speedup vs baseline: 3.0391x; 3.0391x over previous
#include <cuda_runtime.h>
#include <math.h>

// ============================================================================
// HOST-side CG constant computation (runs in kernel_launch, not on device).
// Values are input-independent; they are baked into the graph as kernel args.
// ============================================================================
namespace hostcg {

struct cplx { double re, im; };
static inline cplx cxmul(cplx a, cplx b) {
    cplx r; r.re = a.re * b.re - a.im * b.im; r.im = a.re * b.im + a.im * b.re; return r;
}
static double h_fact(int n) { double r = 1.0; for (int i = 2; i <= n; i++) r *= i; return r; }

static double h_cgc(int j1, int m1, int j2, int m2, int j3, int m3) {
    if (m3 != m1 + m2) return 0.0;
    int vmin = 0;
    if (j2 - j3 - m1 > vmin) vmin = j2 - j3 - m1;
    if (j1 + m2 - j3 > vmin) vmin = j1 + m2 - j3;
    int vmax = j1 + j2 - j3;
    if (j1 - m1 < vmax) vmax = j1 - m1;
    if (j2 + m2 < vmax) vmax = j2 + m2;
    double pref = (2.0 * j3 + 1.0) * h_fact(j3 + j1 - j2) * h_fact(j3 - j1 + j2)
                * h_fact(j1 + j2 - j3) / h_fact(j1 + j2 + j3 + 1);
    pref *= h_fact(j3 + m3) * h_fact(j3 - m3) * h_fact(j1 - m1) * h_fact(j1 + m1)
          * h_fact(j2 - m2) * h_fact(j2 + m2);
    double s = 0.0;
    for (int v = vmin; v <= vmax; v++) {
        double t = 1.0 / (h_fact(v) * h_fact(j1 + j2 - j3 - v) * h_fact(j1 - m1 - v)
                        * h_fact(j2 + m2 - v) * h_fact(j3 - j2 + m1 + v) * h_fact(j3 - j1 - m2 + v));
        s += (v & 1) ? -t : t;
    }
    return sqrt(pref) * s;
}

static void h_qmat(int l, cplx q[5][5]) {
    for (int i = 0; i < 5; i++) for (int j = 0; j < 5; j++) { q[i][j].re = 0.0; q[i][j].im = 0.0; }
    const double is2 = 0.70710678118654752440;
    for (int m = -l; m < 0; m++) {
        q[l + m][l - m].re = is2;
        q[l + m][l + m].im = -is2;
    }
    q[l][l].re = 1.0;
    for (int m = 1; m <= l; m++) {
        double sgn = (m & 1) ? -1.0 : 1.0;
        q[l + m][l + m].re = sgn * is2;
        q[l + m][l - m].im = sgn * is2;
    }
    for (int p = 0; p < l; p++)
        for (int i = 0; i < 5; i++) for (int j = 0; j < 5; j++) {
            double re = q[i][j].re, im = q[i][j].im;
            q[i][j].re = im; q[i][j].im = -re;
        }
}

static void h_so3(int l1, int l2, int l3, float* out) {
    cplx q1[5][5], q2[5][5], q3[5][5];
    h_qmat(l1, q1); h_qmat(l2, q2); h_qmat(l3, q3);
    int d1 = 2 * l1 + 1, d2 = 2 * l2 + 1, d3 = 2 * l3 + 1;
    double C[45];
    double norm = 0.0;
    for (int j = 0; j < d1; j++)
        for (int l = 0; l < d2; l++)
            for (int m = 0; m < d3; m++) {
                double acc = 0.0;
                for (int i = 0; i < d1; i++)
                    for (int k = 0; k < d2; k++) {
                        int n = (i - l1) + (k - l2) + l3;
                        if (n < 0 || n >= d3) continue;
                        double s = h_cgc(l1, i - l1, l2, k - l2, l3, n - l3);
                        if (s == 0.0) continue;
                        cplx t = cxmul(q1[i][j], q2[k][l]);
                        cplx c3; c3.re = q3[n][m].re; c3.im = -q3[n][m].im;
                        t = cxmul(t, c3);
                        acc += t.re * s;
                    }
                C[(j * d2 + l) * d3 + m] = acc;
                norm += acc * acc;
            }
    double inv = 1.0 / sqrt(norm);
    for (int x = 0; x < d1 * d2 * d3; x++) out[x] = (float)(C[x] * inv);
}

} // namespace hostcg

// Kernel parameter struct: CG constants (const-bank, baked into graph).
struct CGParams {
    float c5[45];   // (2,1,1) CG, layout [a(5)][j(3)][k(3)]
    float k[6];     // scalar CG coefficient per combo (combo 5 = 1.0)
};

// ============================================================================
// Packed f32x2 helpers (SASS FFMA2 — 2 FMA per issued instruction)
// ============================================================================
typedef unsigned long long ull;

__device__ __forceinline__ ull pk2(float lo, float hi) {
    ull r; asm("mov.b64 %0, {%1, %2};" : "=l"(r) : "f"(lo), "f"(hi)); return r;
}
__device__ __forceinline__ void fma2(ull& d, ull a, ull b) {
    asm("fma.rn.f32x2 %0, %1, %2, %0;" : "+l"(d) : "l"(a), "l"(b));
}
__device__ __forceinline__ float2 upk2(ull v) {
    float2 f; asm("mov.b64 {%0, %1}, %2;" : "=f"(f.x), "=f"(f.y) : "l"(v)); return f;
}
__device__ __forceinline__ ull lds64(const float* p) {
    return *reinterpret_cast<const ull*>(p);
}

// ============================================================================
// Main edge kernel: one thread per edge.
// ============================================================================
__global__ __launch_bounds__(256, 2)
void edge_tp_kernel(const float* __restrict__ node,
                    const int*   __restrict__ ei,
                    const float* __restrict__ sh0,
                    const float* __restrict__ sh1,
                    const float* __restrict__ sh2,
                    const float* __restrict__ W,
                    float*       __restrict__ out,
                    int E, CGParams P) {
    // Weights (with scalar CG folded in) in smem, o-contiguous so that
    // (w[o], w[o+1]) is a single LDS.64.
    __shared__ __align__(16) float sW[384];   // [6][8][8]
    for (int x = threadIdx.x; x < 384; x += blockDim.x)
        sW[x] = W[x] * P.k[x >> 6];
    __syncthreads();

    int e = blockIdx.x * blockDim.x + threadIdx.x;
    if (e >= E) return;

    int s = __ldg(ei + e);
    int t = __ldg(ei + E + e);

    // gather source node row (32 floats, 128B)
    float f[32];
    const float4* row = reinterpret_cast<const float4*>(node + (size_t)s * 32);
    #pragma unroll
    for (int v = 0; v < 8; v++) {
        float4 r = __ldg(row + v);
        f[4 * v + 0] = r.x; f[4 * v + 1] = r.y; f[4 * v + 2] = r.z; f[4 * v + 3] = r.w;
    }

    float h0  = __ldg(sh0 + e);
    float h1x = __ldg(sh1 + 3 * (size_t)e + 0);
    float h1y = __ldg(sh1 + 3 * (size_t)e + 1);
    float h1z = __ldg(sh1 + 3 * (size_t)e + 2);
    float h2[5];
    #pragma unroll
    for (int a = 0; a < 5; a++) h2[a] = __ldg(sh2 + 5 * (size_t)e + a);

    // S5[j][k] = sum_a C5[a][j][k] * sh2[a]
    float S5[9];
    #pragma unroll
    for (int jk = 0; jk < 9; jk++) {
        float acc = 0.f;
        #pragma unroll
        for (int a = 0; a < 5; a++) acc += P.c5[a * 9 + jk] * h2[a];
        S5[jk] = acc;
    }

    // packed accumulators over output-channel pairs (o, o+1)
    ull ms[4];        // scalar channel
    ull mv[4][3];     // vector channels, component-major
    #pragma unroll
    for (int op = 0; op < 4; op++) {
        ms[op] = 0ull;
        mv[op][0] = 0ull; mv[op][1] = 0ull; mv[op][2] = 0ull;
    }

    #pragma unroll
    for (int i = 0; i < 8; i++) {
        float f0 = f[i];
        float fx = f[8 + 3 * i], fy = f[9 + 3 * i], fz = f[10 + 3 * i];
        // per-input-channel base quantities (CG norms folded into sW)
        float a  = h0 * f0;                                 // (0,0,0)
        float b  = h1x * fx + h1y * fy + h1z * fz;          // (1,1,0) dot
        float p0 = h0 * fx, p1 = h0 * fy, p2 = h0 * fz;     // (0,1,1)
        float q0 = h1x * f0, q1 = h1y * f0, q2 = h1z * f0;  // (1,0,1)
        float r0 = h1y * fz - h1z * fy;                     // (1,1,1) cross
        float r1 = h1z * fx - h1x * fz;
        float r2 = h1x * fy - h1y * fx;
        float u0 = S5[0] * fx + S5[3] * fy + S5[6] * fz;    // (2,1,1) S5^T fv
        float u1 = S5[1] * fx + S5[4] * fy + S5[7] * fz;
        float u2 = S5[2] * fx + S5[5] * fy + S5[8] * fz;

        // duplicate bases into both f32x2 lanes (ALU-pipe movs, fma pipe free)
        ull A  = pk2(a,  a),  B  = pk2(b,  b);
        ull P0 = pk2(p0, p0), P1 = pk2(p1, p1), P2 = pk2(p2, p2);
        ull Q0 = pk2(q0, q0), Q1 = pk2(q1, q1), Q2 = pk2(q2, q2);
        ull R0 = pk2(r0, r0), R1 = pk2(r1, r1), R2 = pk2(r2, r2);
        ull U0 = pk2(u0, u0), U1 = pk2(u1, u1), U2 = pk2(u2, u2);

        const float* wi = sW + i * 8;
        #pragma unroll
        for (int op = 0; op < 4; op++) {
            ull w0 = lds64(wi + 0 * 64 + 2 * op);
            ull w1 = lds64(wi + 1 * 64 + 2 * op);
            ull w2 = lds64(wi + 2 * 64 + 2 * op);
            ull w3 = lds64(wi + 3 * 64 + 2 * op);
            ull w4 = lds64(wi + 4 * 64 + 2 * op);
            ull w5 = lds64(wi + 5 * 64 + 2 * op);
            fma2(ms[op], w0, A);  fma2(ms[op], w3, B);
            fma2(mv[op][0], w1, P0); fma2(mv[op][0], w2, Q0);
            fma2(mv[op][0], w4, R0); fma2(mv[op][0], w5, U0);
            fma2(mv[op][1], w1, P1); fma2(mv[op][1], w2, Q1);
            fma2(mv[op][1], w4, R1); fma2(mv[op][1], w5, U1);
            fma2(mv[op][2], w1, P2); fma2(mv[op][2], w2, Q2);
            fma2(mv[op][2], w4, R2); fma2(mv[op][2], w5, U2);
        }
    }

    // unpack into output-row layout: [8 scalars][o0.xyz o1.xyz ... o7.xyz]
    float msg[32];
    #pragma unroll
    for (int op = 0; op < 4; op++) {
        float2 sp = upk2(ms[op]);
        msg[2 * op] = sp.x; msg[2 * op + 1] = sp.y;
        #pragma unroll
        for (int k = 0; k < 3; k++) {
            float2 vp = upk2(mv[op][k]);
            msg[8 + 3 * (2 * op) + k]     = vp.x;
            msg[8 + 3 * (2 * op + 1) + k] = vp.y;
        }
    }

    // scatter-add: 8x vector float4 reductions (no return)
    float* orow = out + (size_t)t * 32;
    #pragma unroll
    for (int v = 0; v < 8; v++) {
        asm volatile("red.global.add.v4.f32 [%0], {%1, %2, %3, %4};"
                     :: "l"(orow + 4 * v),
                        "f"(msg[4 * v + 0]), "f"(msg[4 * v + 1]),
                        "f"(msg[4 * v + 2]), "f"(msg[4 * v + 3])
                     : "memory");
    }
}

// ============================================================================
// Launch: host computes CG constants, memset output, one edge kernel.
// Graph-capturable: async memset + kernel launch only, no allocations.
// ============================================================================
extern "C" void kernel_launch(void* const* d_in, const int* in_sizes, int n_in,
                              void* d_out, int out_size) {
    const float* node = (const float*)d_in[0];
    const int*   ei   = (const int*)  d_in[1];
    const float* sh0  = (const float*)d_in[2];
    const float* sh1  = (const float*)d_in[3];
    const float* sh2  = (const float*)d_in[4];
    const float* W    = (const float*)d_in[5];
    int E = in_sizes[1] / 2;

    // CG constants on host (input-independent, deterministic)
    CGParams P;
    float tmp[45];
    hostcg::h_so3(0, 0, 0, tmp); P.k[0] = tmp[0];   // scalar
    hostcg::h_so3(0, 1, 1, tmp); P.k[1] = tmp[0];   // k * delta
    hostcg::h_so3(1, 0, 1, tmp); P.k[2] = tmp[0];   // k * delta
    hostcg::h_so3(1, 1, 0, tmp); P.k[3] = tmp[0];   // k * delta
    hostcg::h_so3(1, 1, 1, tmp); P.k[4] = tmp[5];   // k * eps, entry [0][1][2]
    P.k[5] = 1.0f;
    hostcg::h_so3(2, 1, 1, tmp);
    for (int x = 0; x < 45; x++) P.c5[x] = tmp[x];

    cudaMemsetAsync(d_out, 0, (size_t)out_size * sizeof(float), 0);
    int threads = 256;
    int blocks = (E + threads - 1) / threads;
    edge_tp_kernel<<<blocks, threads>>>(node, ei, sh0, sh1, sh2, W, (float*)d_out, E, P);
}

// round 4
// speedup vs baseline: 5.7513x; 1.8924x over previous
#include <cuda_runtime.h>
#include <math.h>

// ============================================================================
// HOST-side CG constant computation (runs in kernel_launch; baked into graph
// as by-value kernel arguments).
// ============================================================================
namespace hostcg {

struct cplx { double re, im; };
static inline cplx cxmul(cplx a, cplx b) {
    cplx r; r.re = a.re * b.re - a.im * b.im; r.im = a.re * b.im + a.im * b.re; return r;
}
static double h_fact(int n) { double r = 1.0; for (int i = 2; i <= n; i++) r *= i; return r; }

static double h_cgc(int j1, int m1, int j2, int m2, int j3, int m3) {
    if (m3 != m1 + m2) return 0.0;
    int vmin = 0;
    if (j2 - j3 - m1 > vmin) vmin = j2 - j3 - m1;
    if (j1 + m2 - j3 > vmin) vmin = j1 + m2 - j3;
    int vmax = j1 + j2 - j3;
    if (j1 - m1 < vmax) vmax = j1 - m1;
    if (j2 + m2 < vmax) vmax = j2 + m2;
    double pref = (2.0 * j3 + 1.0) * h_fact(j3 + j1 - j2) * h_fact(j3 - j1 + j2)
                * h_fact(j1 + j2 - j3) / h_fact(j1 + j2 + j3 + 1);
    pref *= h_fact(j3 + m3) * h_fact(j3 - m3) * h_fact(j1 - m1) * h_fact(j1 + m1)
          * h_fact(j2 - m2) * h_fact(j2 + m2);
    double s = 0.0;
    for (int v = vmin; v <= vmax; v++) {
        double t = 1.0 / (h_fact(v) * h_fact(j1 + j2 - j3 - v) * h_fact(j1 - m1 - v)
                        * h_fact(j2 + m2 - v) * h_fact(j3 - j2 + m1 + v) * h_fact(j3 - j1 - m2 + v));
        s += (v & 1) ? -t : t;
    }
    return sqrt(pref) * s;
}

static void h_qmat(int l, cplx q[5][5]) {
    for (int i = 0; i < 5; i++) for (int j = 0; j < 5; j++) { q[i][j].re = 0.0; q[i][j].im = 0.0; }
    const double is2 = 0.70710678118654752440;
    for (int m = -l; m < 0; m++) {
        q[l + m][l - m].re = is2;
        q[l + m][l + m].im = -is2;
    }
    q[l][l].re = 1.0;
    for (int m = 1; m <= l; m++) {
        double sgn = (m & 1) ? -1.0 : 1.0;
        q[l + m][l + m].re = sgn * is2;
        q[l + m][l - m].im = sgn * is2;
    }
    for (int p = 0; p < l; p++)
        for (int i = 0; i < 5; i++) for (int j = 0; j < 5; j++) {
            double re = q[i][j].re, im = q[i][j].im;
            q[i][j].re = im; q[i][j].im = -re;
        }
}

static void h_so3(int l1, int l2, int l3, float* out) {
    cplx q1[5][5], q2[5][5], q3[5][5];
    h_qmat(l1, q1); h_qmat(l2, q2); h_qmat(l3, q3);
    int d1 = 2 * l1 + 1, d2 = 2 * l2 + 1, d3 = 2 * l3 + 1;
    double C[45];
    double norm = 0.0;
    for (int j = 0; j < d1; j++)
        for (int l = 0; l < d2; l++)
            for (int m = 0; m < d3; m++) {
                double acc = 0.0;
                for (int i = 0; i < d1; i++)
                    for (int k = 0; k < d2; k++) {
                        int n = (i - l1) + (k - l2) + l3;
                        if (n < 0 || n >= d3) continue;
                        double s = h_cgc(l1, i - l1, l2, k - l2, l3, n - l3);
                        if (s == 0.0) continue;
                        cplx t = cxmul(q1[i][j], q2[k][l]);
                        cplx c3; c3.re = q3[n][m].re; c3.im = -q3[n][m].im;
                        t = cxmul(t, c3);
                        acc += t.re * s;
                    }
                C[(j * d2 + l) * d3 + m] = acc;
                norm += acc * acc;
            }
    double inv = 1.0 / sqrt(norm);
    for (int x = 0; x < d1 * d2 * d3; x++) out[x] = (float)(C[x] * inv);
}

} // namespace hostcg

struct CGParams {
    float c5[45];   // (2,1,1) CG, layout [a(5)][j(3)][k(3)]
    float k[6];     // scalar CG coefficient per combo (combo 5 = 1.0)
};

// ============================================================================
// Edge kernel. Block = 128 threads = 4 warps, one edge per thread.
// Warp-cooperative coalesced gather + scatter via padded smem staging.
// ============================================================================
#define TPB   128
#define ROWF  36      // padded row stride in floats (36*4=144B, conflict-free)

__global__ __launch_bounds__(TPB, 3)
void edge_tp_kernel(const float* __restrict__ node,
                    const int*   __restrict__ ei,
                    const float* __restrict__ sh0,
                    const float* __restrict__ sh1,
                    const float* __restrict__ sh2,
                    const float* __restrict__ W,
                    float*       __restrict__ out,
                    int E, CGParams P) {
    // weights rearranged [i(8)][combo(6)][o(8)], CG norm folded in
    __shared__ __align__(16) float sWp[384];
    // per-warp staging: 32 rows x 36 floats
    __shared__ __align__(16) float stage[4][32 * ROWF];

    for (int x = threadIdx.x; x < 384; x += TPB) {
        int c = x >> 6, i = (x >> 3) & 7, o = x & 7;
        sWp[i * 48 + c * 8 + o] = W[x] * P.k[c];
    }
    __syncthreads();

    const unsigned FULL = 0xffffffffu;
    int warp = threadIdx.x >> 5;
    int lane = threadIdx.x & 31;
    int piece = lane & 7;      // float4 index within a 32-float row
    int rsub  = lane >> 3;     // row-within-pass (0..3)
    int ebase = blockIdx.x * TPB + warp * 32;
    int e = ebase + lane;
    bool valid = e < E;
    int ec = valid ? e : 0;

    int s_idx = __ldg(ei + ec);
    int t_idx = __ldg(ei + E + ec);

    float* buf = stage[warp];

    // ---- cooperative coalesced gather: each node row = one 128B line ----
    #pragma unroll
    for (int p = 0; p < 8; p++) {
        int er  = p * 4 + rsub;
        int sid = __shfl_sync(FULL, s_idx, er);
        float4 v = __ldg(reinterpret_cast<const float4*>(node + (size_t)sid * 32) + piece);
        *reinterpret_cast<float4*>(buf + er * ROWF + piece * 4) = v;
    }
    __syncwarp();

    // ---- each thread reads its own row (LDS.128, conflict-free) ----
    float f[32];
    #pragma unroll
    for (int j = 0; j < 8; j++) {
        float4 v = *reinterpret_cast<const float4*>(buf + lane * ROWF + j * 4);
        f[4 * j + 0] = v.x; f[4 * j + 1] = v.y; f[4 * j + 2] = v.z; f[4 * j + 3] = v.w;
    }
    __syncwarp();   // all reads done before buf is reused for msg

    // ---- per-edge SH values ----
    float h0  = __ldg(sh0 + ec);
    float h1x = __ldg(sh1 + 3 * (size_t)ec + 0);
    float h1y = __ldg(sh1 + 3 * (size_t)ec + 1);
    float h1z = __ldg(sh1 + 3 * (size_t)ec + 2);
    float h2[5];
    #pragma unroll
    for (int a = 0; a < 5; a++) h2[a] = __ldg(sh2 + 5 * (size_t)ec + a);

    // S5[j][k] = sum_a C5[a][j][k] * sh2[a]
    float S5[9];
    #pragma unroll
    for (int jk = 0; jk < 9; jk++) {
        float acc = 0.f;
        #pragma unroll
        for (int a = 0; a < 5; a++) acc += P.c5[a * 9 + jk] * h2[a];
        S5[jk] = acc;
    }

    // ---- per-edge tensor product + channel mixing (scalar FFMA) ----
    float msg[32];
    #pragma unroll
    for (int v = 0; v < 32; v++) msg[v] = 0.f;

    #pragma unroll
    for (int i = 0; i < 8; i++) {
        float f0 = f[i];
        float fx = f[8 + 3 * i], fy = f[9 + 3 * i], fz = f[10 + 3 * i];
        float a  = h0 * f0;                                 // (0,0,0)
        float b  = h1x * fx + h1y * fy + h1z * fz;          // (1,1,0) dot
        float p0 = h0 * fx, p1 = h0 * fy, p2 = h0 * fz;     // (0,1,1)
        float q0 = h1x * f0, q1 = h1y * f0, q2 = h1z * f0;  // (1,0,1)
        float r0 = h1y * fz - h1z * fy;                     // (1,1,1) cross
        float r1 = h1z * fx - h1x * fz;
        float r2 = h1x * fy - h1y * fx;
        float u0 = S5[0] * fx + S5[3] * fy + S5[6] * fz;    // (2,1,1)
        float u1 = S5[1] * fx + S5[4] * fy + S5[7] * fz;
        float u2 = S5[2] * fx + S5[5] * fy + S5[8] * fz;

        const float* wi = sWp + i * 48;
        #pragma unroll
        for (int oq = 0; oq < 2; oq++) {
            float4 w0 = *reinterpret_cast<const float4*>(wi +  0 + oq * 4);
            float4 w1 = *reinterpret_cast<const float4*>(wi +  8 + oq * 4);
            float4 w2 = *reinterpret_cast<const float4*>(wi + 16 + oq * 4);
            float4 w3 = *reinterpret_cast<const float4*>(wi + 24 + oq * 4);
            float4 w4 = *reinterpret_cast<const float4*>(wi + 32 + oq * 4);
            float4 w5 = *reinterpret_cast<const float4*>(wi + 40 + oq * 4);
            #pragma unroll
            for (int r = 0; r < 4; r++) {
                int o = oq * 4 + r;
                float W0 = (&w0.x)[r], W1 = (&w1.x)[r], W2 = (&w2.x)[r];
                float W3 = (&w3.x)[r], W4 = (&w4.x)[r], W5 = (&w5.x)[r];
                msg[o] += W0 * a + W3 * b;
                msg[8 + 3 * o + 0] += W1 * p0 + W2 * q0 + W4 * r0 + W5 * u0;
                msg[8 + 3 * o + 1] += W1 * p1 + W2 * q1 + W4 * r1 + W5 * u1;
                msg[8 + 3 * o + 2] += W1 * p2 + W2 * q2 + W4 * r2 + W5 * u2;
            }
        }
    }

    // ---- write msg rows into staging (STS.128, conflict-free) ----
    #pragma unroll
    for (int j = 0; j < 8; j++) {
        float4 v = make_float4(msg[4 * j], msg[4 * j + 1], msg[4 * j + 2], msg[4 * j + 3]);
        *reinterpret_cast<float4*>(buf + lane * ROWF + j * 4) = v;
    }
    __syncwarp();

    // ---- cooperative coalesced scatter: 8 lanes per target row ----
    #pragma unroll
    for (int p = 0; p < 8; p++) {
        int er  = p * 4 + rsub;
        int tid = __shfl_sync(FULL, t_idx, er);
        bool vr = (ebase + er) < E;
        const float* src = buf + er * ROWF + piece * 4;
        float v0 = src[0], v1 = src[1], v2 = src[2], v3 = src[3];
        if (vr) {
            float* dst = out + (size_t)tid * 32 + piece * 4;
            asm volatile("red.global.add.v4.f32 [%0], {%1, %2, %3, %4};"
                         :: "l"(dst), "f"(v0), "f"(v1), "f"(v2), "f"(v3)
                         : "memory");
        }
    }
}

// ============================================================================
// Launch
// ============================================================================
extern "C" void kernel_launch(void* const* d_in, const int* in_sizes, int n_in,
                              void* d_out, int out_size) {
    const float* node = (const float*)d_in[0];
    const int*   ei   = (const int*)  d_in[1];
    const float* sh0  = (const float*)d_in[2];
    const float* sh1  = (const float*)d_in[3];
    const float* sh2  = (const float*)d_in[4];
    const float* W    = (const float*)d_in[5];
    int E = in_sizes[1] / 2;

    CGParams P;
    float tmp[45];
    hostcg::h_so3(0, 0, 0, tmp); P.k[0] = tmp[0];
    hostcg::h_so3(0, 1, 1, tmp); P.k[1] = tmp[0];
    hostcg::h_so3(1, 0, 1, tmp); P.k[2] = tmp[0];
    hostcg::h_so3(1, 1, 0, tmp); P.k[3] = tmp[0];
    hostcg::h_so3(1, 1, 1, tmp); P.k[4] = tmp[5];
    P.k[5] = 1.0f;
    hostcg::h_so3(2, 1, 1, tmp);
    for (int x = 0; x < 45; x++) P.c5[x] = tmp[x];

    cudaMemsetAsync(d_out, 0, (size_t)out_size * sizeof(float), 0);
    int blocks = (E + TPB - 1) / TPB;
    edge_tp_kernel<<<blocks, TPB>>>(node, ei, sh0, sh1, sh2, W, (float*)d_out, E, P);
}

// round 5
// speedup vs baseline: 6.9232x; 1.2037x over previous
#include <cuda_runtime.h>
#include <math.h>

// ============================================================================
// HOST-side CG constant computation (runs in kernel_launch; baked into graph
// as by-value kernel arguments).
// ============================================================================
namespace hostcg {

struct cplx { double re, im; };
static inline cplx cxmul(cplx a, cplx b) {
    cplx r; r.re = a.re * b.re - a.im * b.im; r.im = a.re * b.im + a.im * b.re; return r;
}
static double h_fact(int n) { double r = 1.0; for (int i = 2; i <= n; i++) r *= i; return r; }

static double h_cgc(int j1, int m1, int j2, int m2, int j3, int m3) {
    if (m3 != m1 + m2) return 0.0;
    int vmin = 0;
    if (j2 - j3 - m1 > vmin) vmin = j2 - j3 - m1;
    if (j1 + m2 - j3 > vmin) vmin = j1 + m2 - j3;
    int vmax = j1 + j2 - j3;
    if (j1 - m1 < vmax) vmax = j1 - m1;
    if (j2 + m2 < vmax) vmax = j2 + m2;
    double pref = (2.0 * j3 + 1.0) * h_fact(j3 + j1 - j2) * h_fact(j3 - j1 + j2)
                * h_fact(j1 + j2 - j3) / h_fact(j1 + j2 + j3 + 1);
    pref *= h_fact(j3 + m3) * h_fact(j3 - m3) * h_fact(j1 - m1) * h_fact(j1 + m1)
          * h_fact(j2 - m2) * h_fact(j2 + m2);
    double s = 0.0;
    for (int v = vmin; v <= vmax; v++) {
        double t = 1.0 / (h_fact(v) * h_fact(j1 + j2 - j3 - v) * h_fact(j1 - m1 - v)
                        * h_fact(j2 + m2 - v) * h_fact(j3 - j2 + m1 + v) * h_fact(j3 - j1 - m2 + v));
        s += (v & 1) ? -t : t;
    }
    return sqrt(pref) * s;
}

static void h_qmat(int l, cplx q[5][5]) {
    for (int i = 0; i < 5; i++) for (int j = 0; j < 5; j++) { q[i][j].re = 0.0; q[i][j].im = 0.0; }
    const double is2 = 0.70710678118654752440;
    for (int m = -l; m < 0; m++) {
        q[l + m][l - m].re = is2;
        q[l + m][l + m].im = -is2;
    }
    q[l][l].re = 1.0;
    for (int m = 1; m <= l; m++) {
        double sgn = (m & 1) ? -1.0 : 1.0;
        q[l + m][l + m].re = sgn * is2;
        q[l + m][l - m].im = sgn * is2;
    }
    for (int p = 0; p < l; p++)
        for (int i = 0; i < 5; i++) for (int j = 0; j < 5; j++) {
            double re = q[i][j].re, im = q[i][j].im;
            q[i][j].re = im; q[i][j].im = -re;
        }
}

static void h_so3(int l1, int l2, int l3, float* out) {
    cplx q1[5][5], q2[5][5], q3[5][5];
    h_qmat(l1, q1); h_qmat(l2, q2); h_qmat(l3, q3);
    int d1 = 2 * l1 + 1, d2 = 2 * l2 + 1, d3 = 2 * l3 + 1;
    double C[45];
    double norm = 0.0;
    for (int j = 0; j < d1; j++)
        for (int l = 0; l < d2; l++)
            for (int m = 0; m < d3; m++) {
                double acc = 0.0;
                for (int i = 0; i < d1; i++)
                    for (int k = 0; k < d2; k++) {
                        int n = (i - l1) + (k - l2) + l3;
                        if (n < 0 || n >= d3) continue;
                        double s = h_cgc(l1, i - l1, l2, k - l2, l3, n - l3);
                        if (s == 0.0) continue;
                        cplx t = cxmul(q1[i][j], q2[k][l]);
                        cplx c3; c3.re = q3[n][m].re; c3.im = -q3[n][m].im;
                        t = cxmul(t, c3);
                        acc += t.re * s;
                    }
                C[(j * d2 + l) * d3 + m] = acc;
                norm += acc * acc;
            }
    double inv = 1.0 / sqrt(norm);
    for (int x = 0; x < d1 * d2 * d3; x++) out[x] = (float)(C[x] * inv);
}

} // namespace hostcg

struct CGParams {
    float c5[45];   // (2,1,1) CG, layout [a(5)][j(3)][k(3)]
    float k[6];     // scalar CG coefficient per combo (combo 5 = 1.0)
};

// ============================================================================
// f32x2 helpers: one instruction = 2 fp32 ops (edge-pair packed in lanes)
// ============================================================================
typedef unsigned long long ull;

__device__ __forceinline__ ull pk2(float lo, float hi) {
    ull r; asm("mov.b64 %0, {%1, %2};" : "=l"(r) : "f"(lo), "f"(hi)); return r;
}
__device__ __forceinline__ float2 upk2(ull v) {
    float2 f; asm("mov.b64 {%0, %1}, %2;" : "=f"(f.x), "=f"(f.y) : "l"(v)); return f;
}
__device__ __forceinline__ ull mul2(ull a, ull b) {
    ull r; asm("mul.rn.f32x2 %0, %1, %2;" : "=l"(r) : "l"(a), "l"(b)); return r;
}
__device__ __forceinline__ void fma2(ull& d, ull a, ull b) {
    asm("fma.rn.f32x2 %0, %1, %2, %0;" : "+l"(d) : "l"(a), "l"(b));
}

// ============================================================================
// Edge kernel. Block = 128 threads = 4 warps. 2 edges per thread (64/warp),
// all math packed f32x2 over the edge pair. Warp-cooperative coalesced
// gather + scatter through two per-warp smem staging buffers.
// ============================================================================
#define TPB   128
#define ROWF  36      // padded row stride in floats (144B, conflict-free)

__global__ __launch_bounds__(TPB, 3)
void edge_tp_kernel(const float* __restrict__ node,
                    const int*   __restrict__ ei,
                    const float* __restrict__ sh0,
                    const float* __restrict__ sh1,
                    const float* __restrict__ sh2,
                    const float* __restrict__ W,
                    float*       __restrict__ out,
                    int E, CGParams P) {
    // duplicated weights [i(8)][combo(6)][o(8)] as float2(w,w), CG folded in
    __shared__ __align__(16) float2 sW2[384];
    // per-warp staging: group-a edges and group-b edges, 32 rows x 36 floats
    __shared__ __align__(16) float bufA_s[4][32 * ROWF];
    __shared__ __align__(16) float bufB_s[4][32 * ROWF];

    for (int x = threadIdx.x; x < 384; x += TPB) {
        int c = x >> 6, i = (x >> 3) & 7, o = x & 7;
        float w = W[x] * P.k[c];
        sW2[i * 48 + c * 8 + o] = make_float2(w, w);
    }
    __syncthreads();

    const unsigned FULL = 0xffffffffu;
    int warp  = threadIdx.x >> 5;
    int lane  = threadIdx.x & 31;
    int piece = lane & 7;      // float4 index within a 32-float row
    int rsub  = lane >> 3;     // row-within-pass (0..3)
    int ebase = (blockIdx.x * 4 + warp) * 64;
    int ea = ebase + lane;       if (ea >= E) ea = E - 1;
    int eb = ebase + 32 + lane;  if (eb >= E) eb = E - 1;

    int sa = __ldg(ei + ea);
    int sb = __ldg(ei + eb);
    int ta = __ldg(ei + E + ea);
    int tb = __ldg(ei + E + eb);

    float* bA = bufA_s[warp];
    float* bB = bufB_s[warp];

    // ---- cooperative coalesced gather: each node row = one 128B line ----
    #pragma unroll
    for (int p = 0; p < 8; p++) {
        int er = p * 4 + rsub;
        int ia = __shfl_sync(FULL, sa, er);
        int ib = __shfl_sync(FULL, sb, er);
        float4 va = __ldg(reinterpret_cast<const float4*>(node + (size_t)ia * 32) + piece);
        float4 vb = __ldg(reinterpret_cast<const float4*>(node + (size_t)ib * 32) + piece);
        *reinterpret_cast<float4*>(bA + er * ROWF + piece * 4) = va;
        *reinterpret_cast<float4*>(bB + er * ROWF + piece * 4) = vb;
    }
    __syncwarp();

    // ---- per-edge-pair SH values (packed) ----
    ull H0 = pk2(__ldg(sh0 + ea), __ldg(sh0 + eb));
    float h1xa = __ldg(sh1 + 3 * (size_t)ea + 0), h1xb = __ldg(sh1 + 3 * (size_t)eb + 0);
    float h1ya = __ldg(sh1 + 3 * (size_t)ea + 1), h1yb = __ldg(sh1 + 3 * (size_t)eb + 1);
    float h1za = __ldg(sh1 + 3 * (size_t)ea + 2), h1zb = __ldg(sh1 + 3 * (size_t)eb + 2);
    ull H1X = pk2(h1xa, h1xb), H1Y = pk2(h1ya, h1yb), H1Z = pk2(h1za, h1zb);
    ull NH1X = pk2(-h1xa, -h1xb), NH1Y = pk2(-h1ya, -h1yb), NH1Z = pk2(-h1za, -h1zb);

    // S5[j][k] = sum_a C5[a][j][k] * sh2[a]  (packed over edge pair)
    ull S5[9];
    {
        ull H2[5];
        #pragma unroll
        for (int a = 0; a < 5; a++)
            H2[a] = pk2(__ldg(sh2 + 5 * (size_t)ea + a), __ldg(sh2 + 5 * (size_t)eb + a));
        #pragma unroll
        for (int jk = 0; jk < 9; jk++) {
            ull acc = mul2(pk2(P.c5[jk], P.c5[jk]), H2[0]);
            #pragma unroll
            for (int a = 1; a < 5; a++)
                fma2(acc, pk2(P.c5[a * 9 + jk], P.c5[a * 9 + jk]), H2[a]);
            S5[jk] = acc;
        }
    }

    // ---- packed accumulators: 8 scalar + 8x3 vector outputs ----
    ull MS[8], MV[8][3];
    #pragma unroll
    for (int o = 0; o < 8; o++) {
        MS[o] = 0ull; MV[o][0] = 0ull; MV[o][1] = 0ull; MV[o][2] = 0ull;
    }

    const float* rA = bA + lane * ROWF;
    const float* rB = bB + lane * ROWF;

    #pragma unroll
    for (int i = 0; i < 8; i++) {
        // stream this input channel's features from staging (both edges)
        ull F0 = pk2(rA[i],           rB[i]);
        ull FX = pk2(rA[8 + 3 * i],   rB[8 + 3 * i]);
        ull FY = pk2(rA[9 + 3 * i],   rB[9 + 3 * i]);
        ull FZ = pk2(rA[10 + 3 * i],  rB[10 + 3 * i]);

        // base quantities (CG norms folded into sW2)
        ull A  = mul2(H0, F0);                               // (0,0,0)
        ull B  = mul2(H1X, FX); fma2(B, H1Y, FY); fma2(B, H1Z, FZ);   // (1,1,0)
        ull P0 = mul2(H0, FX), P1 = mul2(H0, FY), P2 = mul2(H0, FZ);  // (0,1,1)
        ull Q0 = mul2(H1X, F0), Q1 = mul2(H1Y, F0), Q2 = mul2(H1Z, F0); // (1,0,1)
        ull R0 = mul2(H1Y, FZ); fma2(R0, NH1Z, FY);          // (1,1,1) cross
        ull R1 = mul2(H1Z, FX); fma2(R1, NH1X, FZ);
        ull R2 = mul2(H1X, FY); fma2(R2, NH1Y, FX);
        ull U0 = mul2(S5[0], FX); fma2(U0, S5[3], FY); fma2(U0, S5[6], FZ); // (2,1,1)
        ull U1 = mul2(S5[1], FX); fma2(U1, S5[4], FY); fma2(U1, S5[7], FZ);
        ull U2 = mul2(S5[2], FX); fma2(U2, S5[5], FY); fma2(U2, S5[8], FZ);

        const float2* wi = sW2 + i * 48;
        #pragma unroll
        for (int op = 0; op < 4; op++) {
            // one LDS.128 per combo = duplicated weights for o=2op and 2op+1
            ulonglong2 W0 = *reinterpret_cast<const ulonglong2*>(wi + 0 * 8 + 2 * op);
            ulonglong2 W1 = *reinterpret_cast<const ulonglong2*>(wi + 1 * 8 + 2 * op);
            ulonglong2 W2 = *reinterpret_cast<const ulonglong2*>(wi + 2 * 8 + 2 * op);
            ulonglong2 W3 = *reinterpret_cast<const ulonglong2*>(wi + 3 * 8 + 2 * op);
            ulonglong2 W4 = *reinterpret_cast<const ulonglong2*>(wi + 4 * 8 + 2 * op);
            ulonglong2 W5 = *reinterpret_cast<const ulonglong2*>(wi + 5 * 8 + 2 * op);
            int o0 = 2 * op, o1 = 2 * op + 1;
            fma2(MS[o0], W0.x, A); fma2(MS[o0], W3.x, B);
            fma2(MV[o0][0], W1.x, P0); fma2(MV[o0][0], W2.x, Q0);
            fma2(MV[o0][0], W4.x, R0); fma2(MV[o0][0], W5.x, U0);
            fma2(MV[o0][1], W1.x, P1); fma2(MV[o0][1], W2.x, Q1);
            fma2(MV[o0][1], W4.x, R1); fma2(MV[o0][1], W5.x, U1);
            fma2(MV[o0][2], W1.x, P2); fma2(MV[o0][2], W2.x, Q2);
            fma2(MV[o0][2], W4.x, R2); fma2(MV[o0][2], W5.x, U2);
            fma2(MS[o1], W0.y, A); fma2(MS[o1], W3.y, B);
            fma2(MV[o1][0], W1.y, P0); fma2(MV[o1][0], W2.y, Q0);
            fma2(MV[o1][0], W4.y, R0); fma2(MV[o1][0], W5.y, U0);
            fma2(MV[o1][1], W1.y, P1); fma2(MV[o1][1], W2.y, Q1);
            fma2(MV[o1][1], W4.y, R1); fma2(MV[o1][1], W5.y, U1);
            fma2(MV[o1][2], W1.y, P2); fma2(MV[o1][2], W2.y, Q2);
            fma2(MV[o1][2], W4.y, R2); fma2(MV[o1][2], W5.y, U2);
        }
    }
    __syncwarp();   // staging reads complete before overwrite

    // ---- unpack msg rows into both staging buffers (STS.128) ----
    {
        float* wA = bA + lane * ROWF;
        float* wB = bB + lane * ROWF;
        // msg layout: [0..7]=MS, [8+3o+k]=MV[o][k]
        #pragma unroll
        for (int jq = 0; jq < 8; jq++) {
            float4 a4, b4;
            #pragma unroll
            for (int t = 0; t < 4; t++) {
                int j = 4 * jq + t;
                ull m = (j < 8) ? MS[j] : MV[(j - 8) / 3][(j - 8) % 3];
                float2 f = upk2(m);
                (&a4.x)[t] = f.x;
                (&b4.x)[t] = f.y;
            }
            *reinterpret_cast<float4*>(wA + 4 * jq) = a4;
            *reinterpret_cast<float4*>(wB + 4 * jq) = b4;
        }
    }
    __syncwarp();

    // ---- cooperative coalesced scatter: 8 lanes per target row ----
    #pragma unroll
    for (int p = 0; p < 16; p++) {
        int row = (p & 7) * 4 + rsub;          // 0..31
        int er  = (p < 8) ? row : row + 32;    // edge offset within warp
        int tidx = __shfl_sync(FULL, (p < 8) ? ta : tb, row);
        const float* src = ((p < 8) ? bA : bB) + row * ROWF + piece * 4;
        float4 v = *reinterpret_cast<const float4*>(src);
        if (ebase + er < E) {
            float* dst = out + (size_t)tidx * 32 + piece * 4;
            asm volatile("red.global.add.v4.f32 [%0], {%1, %2, %3, %4};"
                         :: "l"(dst), "f"(v.x), "f"(v.y), "f"(v.z), "f"(v.w)
                         : "memory");
        }
    }
}

// ============================================================================
// Launch
// ============================================================================
extern "C" void kernel_launch(void* const* d_in, const int* in_sizes, int n_in,
                              void* d_out, int out_size) {
    const float* node = (const float*)d_in[0];
    const int*   ei   = (const int*)  d_in[1];
    const float* sh0  = (const float*)d_in[2];
    const float* sh1  = (const float*)d_in[3];
    const float* sh2  = (const float*)d_in[4];
    const float* W    = (const float*)d_in[5];
    int E = in_sizes[1] / 2;

    CGParams P;
    float tmp[45];
    hostcg::h_so3(0, 0, 0, tmp); P.k[0] = tmp[0];
    hostcg::h_so3(0, 1, 1, tmp); P.k[1] = tmp[0];
    hostcg::h_so3(1, 0, 1, tmp); P.k[2] = tmp[0];
    hostcg::h_so3(1, 1, 0, tmp); P.k[3] = tmp[0];
    hostcg::h_so3(1, 1, 1, tmp); P.k[4] = tmp[5];
    P.k[5] = 1.0f;
    hostcg::h_so3(2, 1, 1, tmp);
    for (int x = 0; x < 45; x++) P.c5[x] = tmp[x];

    cudaMemsetAsync(d_out, 0, (size_t)out_size * sizeof(float), 0);
    int blocks = (E + 2 * TPB - 1) / (2 * TPB);
    edge_tp_kernel<<<blocks, TPB>>>(node, ei, sh0, sh1, sh2, W, (float*)d_out, E, P);
}

// round 6
// speedup vs baseline: 6.9433x; 1.0029x over previous
#include <cuda_runtime.h>
#include <math.h>

// ============================================================================
// HOST-side CG constant computation (runs in kernel_launch; baked into graph
// as by-value kernel arguments).
// ============================================================================
namespace hostcg {

struct cplx { double re, im; };
static inline cplx cxmul(cplx a, cplx b) {
    cplx r; r.re = a.re * b.re - a.im * b.im; r.im = a.re * b.im + a.im * b.re; return r;
}
static double h_fact(int n) { double r = 1.0; for (int i = 2; i <= n; i++) r *= i; return r; }

static double h_cgc(int j1, int m1, int j2, int m2, int j3, int m3) {
    if (m3 != m1 + m2) return 0.0;
    int vmin = 0;
    if (j2 - j3 - m1 > vmin) vmin = j2 - j3 - m1;
    if (j1 + m2 - j3 > vmin) vmin = j1 + m2 - j3;
    int vmax = j1 + j2 - j3;
    if (j1 - m1 < vmax) vmax = j1 - m1;
    if (j2 + m2 < vmax) vmax = j2 + m2;
    double pref = (2.0 * j3 + 1.0) * h_fact(j3 + j1 - j2) * h_fact(j3 - j1 + j2)
                * h_fact(j1 + j2 - j3) / h_fact(j1 + j2 + j3 + 1);
    pref *= h_fact(j3 + m3) * h_fact(j3 - m3) * h_fact(j1 - m1) * h_fact(j1 + m1)
          * h_fact(j2 - m2) * h_fact(j2 + m2);
    double s = 0.0;
    for (int v = vmin; v <= vmax; v++) {
        double t = 1.0 / (h_fact(v) * h_fact(j1 + j2 - j3 - v) * h_fact(j1 - m1 - v)
                        * h_fact(j2 + m2 - v) * h_fact(j3 - j2 + m1 + v) * h_fact(j3 - j1 - m2 + v));
        s += (v & 1) ? -t : t;
    }
    return sqrt(pref) * s;
}

static void h_qmat(int l, cplx q[5][5]) {
    for (int i = 0; i < 5; i++) for (int j = 0; j < 5; j++) { q[i][j].re = 0.0; q[i][j].im = 0.0; }
    const double is2 = 0.70710678118654752440;
    for (int m = -l; m < 0; m++) {
        q[l + m][l - m].re = is2;
        q[l + m][l + m].im = -is2;
    }
    q[l][l].re = 1.0;
    for (int m = 1; m <= l; m++) {
        double sgn = (m & 1) ? -1.0 : 1.0;
        q[l + m][l + m].re = sgn * is2;
        q[l + m][l - m].im = sgn * is2;
    }
    for (int p = 0; p < l; p++)
        for (int i = 0; i < 5; i++) for (int j = 0; j < 5; j++) {
            double re = q[i][j].re, im = q[i][j].im;
            q[i][j].re = im; q[i][j].im = -re;
        }
}

static void h_so3(int l1, int l2, int l3, float* out) {
    cplx q1[5][5], q2[5][5], q3[5][5];
    h_qmat(l1, q1); h_qmat(l2, q2); h_qmat(l3, q3);
    int d1 = 2 * l1 + 1, d2 = 2 * l2 + 1, d3 = 2 * l3 + 1;
    double C[45];
    double norm = 0.0;
    for (int j = 0; j < d1; j++)
        for (int l = 0; l < d2; l++)
            for (int m = 0; m < d3; m++) {
                double acc = 0.0;
                for (int i = 0; i < d1; i++)
                    for (int k = 0; k < d2; k++) {
                        int n = (i - l1) + (k - l2) + l3;
                        if (n < 0 || n >= d3) continue;
                        double s = h_cgc(l1, i - l1, l2, k - l2, l3, n - l3);
                        if (s == 0.0) continue;
                        cplx t = cxmul(q1[i][j], q2[k][l]);
                        cplx c3; c3.re = q3[n][m].re; c3.im = -q3[n][m].im;
                        t = cxmul(t, c3);
                        acc += t.re * s;
                    }
                C[(j * d2 + l) * d3 + m] = acc;
                norm += acc * acc;
            }
    double inv = 1.0 / sqrt(norm);
    for (int x = 0; x < d1 * d2 * d3; x++) out[x] = (float)(C[x] * inv);
}

} // namespace hostcg

struct CGParams {
    float c5[45];   // (2,1,1) CG, layout [a(5)][j(3)][k(3)]
    float k[6];     // scalar CG coefficient per combo (combo 5 = 1.0)
};

// ============================================================================
// f32x2 helpers: one instruction = 2 fp32 ops (edge-pair packed in lanes)
// ============================================================================
typedef unsigned long long ull;

__device__ __forceinline__ ull pk2(float lo, float hi) {
    ull r; asm("mov.b64 %0, {%1, %2};" : "=l"(r) : "f"(lo), "f"(hi)); return r;
}
__device__ __forceinline__ float2 upk2(ull v) {
    float2 f; asm("mov.b64 {%0, %1}, %2;" : "=f"(f.x), "=f"(f.y) : "l"(v)); return f;
}
__device__ __forceinline__ ull mul2(ull a, ull b) {
    ull r; asm("mul.rn.f32x2 %0, %1, %2;" : "=l"(r) : "l"(a), "l"(b)); return r;
}
__device__ __forceinline__ void fma2(ull& d, ull a, ull b) {
    asm("fma.rn.f32x2 %0, %1, %2, %0;" : "+l"(d) : "l"(a), "l"(b));
}

// ============================================================================
// Edge kernel. Block = 128 threads = 4 warps. 2 edges per thread (64/warp),
// all math packed f32x2 over the edge pair. Warp-cooperative coalesced
// gather + scatter through two per-warp smem staging buffers.
// ============================================================================
#define TPB   128
#define ROWF  36      // padded row stride in floats (144B, conflict-free)

__global__ __launch_bounds__(TPB, 3)
void edge_tp_kernel(const float* __restrict__ node,
                    const int*   __restrict__ ei,
                    const float* __restrict__ sh0,
                    const float* __restrict__ sh1,
                    const float* __restrict__ sh2,
                    const float* __restrict__ W,
                    float*       __restrict__ out,
                    int E, CGParams P) {
    // duplicated weights [i(8)][combo(6)][o(8)] as float2(w,w), CG folded in
    __shared__ __align__(16) float2 sW2[384];
    // per-warp staging: group-a edges and group-b edges, 32 rows x 36 floats
    __shared__ __align__(16) float bufA_s[4][32 * ROWF];
    __shared__ __align__(16) float bufB_s[4][32 * ROWF];

    for (int x = threadIdx.x; x < 384; x += TPB) {
        int c = x >> 6, i = (x >> 3) & 7, o = x & 7;
        float w = W[x] * P.k[c];
        sW2[i * 48 + c * 8 + o] = make_float2(w, w);
    }
    __syncthreads();

    const unsigned FULL = 0xffffffffu;
    int warp  = threadIdx.x >> 5;
    int lane  = threadIdx.x & 31;
    int piece = lane & 7;      // float4 index within a 32-float row
    int rsub  = lane >> 3;     // row-within-pass (0..3)
    int ebase = (blockIdx.x * 4 + warp) * 64;
    int ea = ebase + lane;       if (ea >= E) ea = E - 1;
    int eb = ebase + 32 + lane;  if (eb >= E) eb = E - 1;

    int sa = __ldg(ei + ea);
    int sb = __ldg(ei + eb);
    int ta = __ldg(ei + E + ea);
    int tb = __ldg(ei + E + eb);

    float* bA = bufA_s[warp];
    float* bB = bufB_s[warp];

    // ---- cooperative coalesced gather: each node row = one 128B line ----
    #pragma unroll
    for (int p = 0; p < 8; p++) {
        int er = p * 4 + rsub;
        int ia = __shfl_sync(FULL, sa, er);
        int ib = __shfl_sync(FULL, sb, er);
        float4 va = __ldg(reinterpret_cast<const float4*>(node + (size_t)ia * 32) + piece);
        float4 vb = __ldg(reinterpret_cast<const float4*>(node + (size_t)ib * 32) + piece);
        *reinterpret_cast<float4*>(bA + er * ROWF + piece * 4) = va;
        *reinterpret_cast<float4*>(bB + er * ROWF + piece * 4) = vb;
    }
    __syncwarp();

    // ---- per-edge-pair SH values (packed) ----
    ull H0 = pk2(__ldg(sh0 + ea), __ldg(sh0 + eb));
    float h1xa = __ldg(sh1 + 3 * (size_t)ea + 0), h1xb = __ldg(sh1 + 3 * (size_t)eb + 0);
    float h1ya = __ldg(sh1 + 3 * (size_t)ea + 1), h1yb = __ldg(sh1 + 3 * (size_t)eb + 1);
    float h1za = __ldg(sh1 + 3 * (size_t)ea + 2), h1zb = __ldg(sh1 + 3 * (size_t)eb + 2);
    ull H1X = pk2(h1xa, h1xb), H1Y = pk2(h1ya, h1yb), H1Z = pk2(h1za, h1zb);
    ull NH1X = pk2(-h1xa, -h1xb), NH1Y = pk2(-h1ya, -h1yb), NH1Z = pk2(-h1za, -h1zb);

    // S5[j][k] = sum_a C5[a][j][k] * sh2[a]  (packed over edge pair)
    ull S5[9];
    {
        ull H2[5];
        #pragma unroll
        for (int a = 0; a < 5; a++)
            H2[a] = pk2(__ldg(sh2 + 5 * (size_t)ea + a), __ldg(sh2 + 5 * (size_t)eb + a));
        #pragma unroll
        for (int jk = 0; jk < 9; jk++) {
            ull acc = mul2(pk2(P.c5[jk], P.c5[jk]), H2[0]);
            #pragma unroll
            for (int a = 1; a < 5; a++)
                fma2(acc, pk2(P.c5[a * 9 + jk], P.c5[a * 9 + jk]), H2[a]);
            S5[jk] = acc;
        }
    }

    // ---- packed accumulators: 8 scalar + 8x3 vector outputs ----
    ull MS[8], MV[8][3];
    #pragma unroll
    for (int o = 0; o < 8; o++) {
        MS[o] = 0ull; MV[o][0] = 0ull; MV[o][1] = 0ull; MV[o][2] = 0ull;
    }

    const float* rA = bA + lane * ROWF;
    const float* rB = bB + lane * ROWF;

    #pragma unroll
    for (int i = 0; i < 8; i++) {
        // stream this input channel's features from staging (both edges)
        ull F0 = pk2(rA[i],           rB[i]);
        ull FX = pk2(rA[8 + 3 * i],   rB[8 + 3 * i]);
        ull FY = pk2(rA[9 + 3 * i],   rB[9 + 3 * i]);
        ull FZ = pk2(rA[10 + 3 * i],  rB[10 + 3 * i]);

        // base quantities (CG norms folded into sW2)
        ull A  = mul2(H0, F0);                               // (0,0,0)
        ull B  = mul2(H1X, FX); fma2(B, H1Y, FY); fma2(B, H1Z, FZ);   // (1,1,0)
        ull P0 = mul2(H0, FX), P1 = mul2(H0, FY), P2 = mul2(H0, FZ);  // (0,1,1)
        ull Q0 = mul2(H1X, F0), Q1 = mul2(H1Y, F0), Q2 = mul2(H1Z, F0); // (1,0,1)
        ull R0 = mul2(H1Y, FZ); fma2(R0, NH1Z, FY);          // (1,1,1) cross
        ull R1 = mul2(H1Z, FX); fma2(R1, NH1X, FZ);
        ull R2 = mul2(H1X, FY); fma2(R2, NH1Y, FX);
        ull U0 = mul2(S5[0], FX); fma2(U0, S5[3], FY); fma2(U0, S5[6], FZ); // (2,1,1)
        ull U1 = mul2(S5[1], FX); fma2(U1, S5[4], FY); fma2(U1, S5[7], FZ);
        ull U2 = mul2(S5[2], FX); fma2(U2, S5[5], FY); fma2(U2, S5[8], FZ);

        const float2* wi = sW2 + i * 48;
        #pragma unroll
        for (int op = 0; op < 4; op++) {
            // one LDS.128 per combo = duplicated weights for o=2op and 2op+1
            ulonglong2 W0 = *reinterpret_cast<const ulonglong2*>(wi + 0 * 8 + 2 * op);
            ulonglong2 W1 = *reinterpret_cast<const ulonglong2*>(wi + 1 * 8 + 2 * op);
            ulonglong2 W2 = *reinterpret_cast<const ulonglong2*>(wi + 2 * 8 + 2 * op);
            ulonglong2 W3 = *reinterpret_cast<const ulonglong2*>(wi + 3 * 8 + 2 * op);
            ulonglong2 W4 = *reinterpret_cast<const ulonglong2*>(wi + 4 * 8 + 2 * op);
            ulonglong2 W5 = *reinterpret_cast<const ulonglong2*>(wi + 5 * 8 + 2 * op);
            int o0 = 2 * op, o1 = 2 * op + 1;
            fma2(MS[o0], W0.x, A); fma2(MS[o0], W3.x, B);
            fma2(MV[o0][0], W1.x, P0); fma2(MV[o0][0], W2.x, Q0);
            fma2(MV[o0][0], W4.x, R0); fma2(MV[o0][0], W5.x, U0);
            fma2(MV[o0][1], W1.x, P1); fma2(MV[o0][1], W2.x, Q1);
            fma2(MV[o0][1], W4.x, R1); fma2(MV[o0][1], W5.x, U1);
            fma2(MV[o0][2], W1.x, P2); fma2(MV[o0][2], W2.x, Q2);
            fma2(MV[o0][2], W4.x, R2); fma2(MV[o0][2], W5.x, U2);
            fma2(MS[o1], W0.y, A); fma2(MS[o1], W3.y, B);
            fma2(MV[o1][0], W1.y, P0); fma2(MV[o1][0], W2.y, Q0);
            fma2(MV[o1][0], W4.y, R0); fma2(MV[o1][0], W5.y, U0);
            fma2(MV[o1][1], W1.y, P1); fma2(MV[o1][1], W2.y, Q1);
            fma2(MV[o1][1], W4.y, R1); fma2(MV[o1][1], W5.y, U1);
            fma2(MV[o1][2], W1.y, P2); fma2(MV[o1][2], W2.y, Q2);
            fma2(MV[o1][2], W4.y, R2); fma2(MV[o1][2], W5.y, U2);
        }
    }
    __syncwarp();   // staging reads complete before overwrite

    // ---- unpack msg rows into both staging buffers (STS.128) ----
    {
        float* wA = bA + lane * ROWF;
        float* wB = bB + lane * ROWF;
        // msg layout: [0..7]=MS, [8+3o+k]=MV[o][k]
        #pragma unroll
        for (int jq = 0; jq < 8; jq++) {
            float4 a4, b4;
            #pragma unroll
            for (int t = 0; t < 4; t++) {
                int j = 4 * jq + t;
                ull m = (j < 8) ? MS[j] : MV[(j - 8) / 3][(j - 8) % 3];
                float2 f = upk2(m);
                (&a4.x)[t] = f.x;
                (&b4.x)[t] = f.y;
            }
            *reinterpret_cast<float4*>(wA + 4 * jq) = a4;
            *reinterpret_cast<float4*>(wB + 4 * jq) = b4;
        }
    }
    __syncwarp();

    // ---- cooperative coalesced scatter: 8 lanes per target row ----
    #pragma unroll
    for (int p = 0; p < 16; p++) {
        int row = (p & 7) * 4 + rsub;          // 0..31
        int er  = (p < 8) ? row : row + 32;    // edge offset within warp
        int tidx = __shfl_sync(FULL, (p < 8) ? ta : tb, row);
        const float* src = ((p < 8) ? bA : bB) + row * ROWF + piece * 4;
        float4 v = *reinterpret_cast<const float4*>(src);
        if (ebase + er < E) {
            float* dst = out + (size_t)tidx * 32 + piece * 4;
            asm volatile("red.global.add.v4.f32 [%0], {%1, %2, %3, %4};"
                         :: "l"(dst), "f"(v.x), "f"(v.y), "f"(v.z), "f"(v.w)
                         : "memory");
        }
    }
}

// ============================================================================
// Launch
// ============================================================================
extern "C" void kernel_launch(void* const* d_in, const int* in_sizes, int n_in,
                              void* d_out, int out_size) {
    const float* node = (const float*)d_in[0];
    const int*   ei   = (const int*)  d_in[1];
    const float* sh0  = (const float*)d_in[2];
    const float* sh1  = (const float*)d_in[3];
    const float* sh2  = (const float*)d_in[4];
    const float* W    = (const float*)d_in[5];
    int E = in_sizes[1] / 2;

    CGParams P;
    float tmp[45];
    hostcg::h_so3(0, 0, 0, tmp); P.k[0] = tmp[0];
    hostcg::h_so3(0, 1, 1, tmp); P.k[1] = tmp[0];
    hostcg::h_so3(1, 0, 1, tmp); P.k[2] = tmp[0];
    hostcg::h_so3(1, 1, 0, tmp); P.k[3] = tmp[0];
    hostcg::h_so3(1, 1, 1, tmp); P.k[4] = tmp[5];
    P.k[5] = 1.0f;
    hostcg::h_so3(2, 1, 1, tmp);
    for (int x = 0; x < 45; x++) P.c5[x] = tmp[x];

    cudaMemsetAsync(d_out, 0, (size_t)out_size * sizeof(float), 0);
    int blocks = (E + 2 * TPB - 1) / (2 * TPB);
    edge_tp_kernel<<<blocks, TPB>>>(node, ei, sh0, sh1, sh2, W, (float*)d_out, E, P);
}

// round 7
// speedup vs baseline: 7.2460x; 1.0436x over previous
#include <cuda_runtime.h>
#include <math.h>

// ============================================================================
// HOST-side CG constant computation (runs in kernel_launch; baked into graph
// as by-value kernel arguments).
// ============================================================================
namespace hostcg {

struct cplx { double re, im; };
static inline cplx cxmul(cplx a, cplx b) {
    cplx r; r.re = a.re * b.re - a.im * b.im; r.im = a.re * b.im + a.im * b.re; return r;
}
static double h_fact(int n) { double r = 1.0; for (int i = 2; i <= n; i++) r *= i; return r; }

static double h_cgc(int j1, int m1, int j2, int m2, int j3, int m3) {
    if (m3 != m1 + m2) return 0.0;
    int vmin = 0;
    if (j2 - j3 - m1 > vmin) vmin = j2 - j3 - m1;
    if (j1 + m2 - j3 > vmin) vmin = j1 + m2 - j3;
    int vmax = j1 + j2 - j3;
    if (j1 - m1 < vmax) vmax = j1 - m1;
    if (j2 + m2 < vmax) vmax = j2 + m2;
    double pref = (2.0 * j3 + 1.0) * h_fact(j3 + j1 - j2) * h_fact(j3 - j1 + j2)
                * h_fact(j1 + j2 - j3) / h_fact(j1 + j2 + j3 + 1);
    pref *= h_fact(j3 + m3) * h_fact(j3 - m3) * h_fact(j1 - m1) * h_fact(j1 + m1)
          * h_fact(j2 - m2) * h_fact(j2 + m2);
    double s = 0.0;
    for (int v = vmin; v <= vmax; v++) {
        double t = 1.0 / (h_fact(v) * h_fact(j1 + j2 - j3 - v) * h_fact(j1 - m1 - v)
                        * h_fact(j2 + m2 - v) * h_fact(j3 - j2 + m1 + v) * h_fact(j3 - j1 - m2 + v));
        s += (v & 1) ? -t : t;
    }
    return sqrt(pref) * s;
}

static void h_qmat(int l, cplx q[5][5]) {
    for (int i = 0; i < 5; i++) for (int j = 0; j < 5; j++) { q[i][j].re = 0.0; q[i][j].im = 0.0; }
    const double is2 = 0.70710678118654752440;
    for (int m = -l; m < 0; m++) {
        q[l + m][l - m].re = is2;
        q[l + m][l + m].im = -is2;
    }
    q[l][l].re = 1.0;
    for (int m = 1; m <= l; m++) {
        double sgn = (m & 1) ? -1.0 : 1.0;
        q[l + m][l + m].re = sgn * is2;
        q[l + m][l - m].im = sgn * is2;
    }
    for (int p = 0; p < l; p++)
        for (int i = 0; i < 5; i++) for (int j = 0; j < 5; j++) {
            double re = q[i][j].re, im = q[i][j].im;
            q[i][j].re = im; q[i][j].im = -re;
        }
}

static void h_so3(int l1, int l2, int l3, float* out) {
    cplx q1[5][5], q2[5][5], q3[5][5];
    h_qmat(l1, q1); h_qmat(l2, q2); h_qmat(l3, q3);
    int d1 = 2 * l1 + 1, d2 = 2 * l2 + 1, d3 = 2 * l3 + 1;
    double C[45];
    double norm = 0.0;
    for (int j = 0; j < d1; j++)
        for (int l = 0; l < d2; l++)
            for (int m = 0; m < d3; m++) {
                double acc = 0.0;
                for (int i = 0; i < d1; i++)
                    for (int k = 0; k < d2; k++) {
                        int n = (i - l1) + (k - l2) + l3;
                        if (n < 0 || n >= d3) continue;
                        double s = h_cgc(l1, i - l1, l2, k - l2, l3, n - l3);
                        if (s == 0.0) continue;
                        cplx t = cxmul(q1[i][j], q2[k][l]);
                        cplx c3; c3.re = q3[n][m].re; c3.im = -q3[n][m].im;
                        t = cxmul(t, c3);
                        acc += t.re * s;
                    }
                C[(j * d2 + l) * d3 + m] = acc;
                norm += acc * acc;
            }
    double inv = 1.0 / sqrt(norm);
    for (int x = 0; x < d1 * d2 * d3; x++) out[x] = (float)(C[x] * inv);
}

} // namespace hostcg

struct CGParams {
    float c5[45];   // (2,1,1) CG, layout [a(5)][j(3)][k(3)]
    float k[6];     // scalar CG coefficient per combo (combo 5 = 1.0)
};

// ============================================================================
// f32x2 helpers: one instruction = 2 fp32 ops (edge-pair packed in lanes)
// ============================================================================
typedef unsigned long long ull;

__device__ __forceinline__ ull pk2(float lo, float hi) {
    ull r; asm("mov.b64 %0, {%1, %2};" : "=l"(r) : "f"(lo), "f"(hi)); return r;
}
__device__ __forceinline__ float2 upk2(ull v) {
    float2 f; asm("mov.b64 {%0, %1}, %2;" : "=f"(f.x), "=f"(f.y) : "l"(v)); return f;
}
__device__ __forceinline__ ull mul2(ull a, ull b) {
    ull r; asm("mul.rn.f32x2 %0, %1, %2;" : "=l"(r) : "l"(a), "l"(b)); return r;
}
__device__ __forceinline__ void fma2(ull& d, ull a, ull b) {
    asm("fma.rn.f32x2 %0, %1, %2, %0;" : "+l"(d) : "l"(a), "l"(b));
}

// ============================================================================
// Staging layout:
//   Interleaved pair buffer: row per edge-pair lane, stride PSTR=70 floats.
//   Feature pair c (edge a, edge b adjacent) at word woff(c):
//     piece p = c>>2,  woff = 8p + 4*(p>>2) + 2*(c&3)
//   Stride 70 (mod 32 = 6) + piece swizzle => ALL accesses bank-conflict-free:
//     - feature LDS.64 reads   (16-lane phase: 6*lane distinct)
//     - gather STS.64 writes   (per phase: {6er+f(p)} U {6er+6+f(p)} distinct)
//   After mixing, the same smem (union) is reused as two 32x36 scatter
//   buffers (R4-proven conflict-free float4 layout).
// ============================================================================
#define TPB   128
#define PSTR  70              // interleaved row stride (floats)
#define ROWF  36              // scatter staging row stride (floats)
#define UNIF  2304            // union floats/warp: max(32*70=2240, 2*32*36=2304)

__device__ __forceinline__ constexpr int woff(int c) {
    return 8 * (c >> 2) + 4 * (c >> 4) + 2 * (c & 3);
}

__global__ __launch_bounds__(TPB, 3)
void edge_tp_kernel(const float* __restrict__ node,
                    const int*   __restrict__ ei,
                    const float* __restrict__ sh0,
                    const float* __restrict__ sh1,
                    const float* __restrict__ sh2,
                    const float* __restrict__ W,
                    float*       __restrict__ out,
                    int E, CGParams P) {
    // duplicated weights [i(8)][combo(6)][o(8)] as float2(w,w), CG folded in
    __shared__ __align__(16) float2 sW2[384];
    // per-warp union: interleaved gather stage OR scatter stage
    __shared__ __align__(16) float uni[4][UNIF];

    for (int x = threadIdx.x; x < 384; x += TPB) {
        int c = x >> 6, i = (x >> 3) & 7, o = x & 7;
        float w = W[x] * P.k[c];
        sW2[i * 48 + c * 8 + o] = make_float2(w, w);
    }
    __syncthreads();

    const unsigned FULL = 0xffffffffu;
    int warp  = threadIdx.x >> 5;
    int lane  = threadIdx.x & 31;
    int piece = lane & 7;      // float4 index within a 32-float row
    int rsub  = lane >> 3;     // row-within-pass (0..3)
    int ebase = (blockIdx.x * 4 + warp) * 64;
    int ea = ebase + lane;       if (ea >= E) ea = E - 1;
    int eb = ebase + 32 + lane;  if (eb >= E) eb = E - 1;

    int sa = __ldg(ei + ea);
    int sb = __ldg(ei + eb);
    int ta = __ldg(ei + E + ea);
    int tb = __ldg(ei + E + eb);

    float* bP = uni[warp];
    int pieceoff = 8 * piece + 4 * (piece >> 2);   // f(piece)

    // ---- cooperative coalesced gather, pair-interleaved STS.64 ----
    #pragma unroll
    for (int p = 0; p < 8; p++) {
        int er = p * 4 + rsub;
        int ia = __shfl_sync(FULL, sa, er);
        int ib = __shfl_sync(FULL, sb, er);
        float4 va = __ldg(reinterpret_cast<const float4*>(node + (size_t)ia * 32) + piece);
        float4 vb = __ldg(reinterpret_cast<const float4*>(node + (size_t)ib * 32) + piece);
        float* dst = bP + er * PSTR + pieceoff;
        *reinterpret_cast<float2*>(dst + 0) = make_float2(va.x, vb.x);
        *reinterpret_cast<float2*>(dst + 2) = make_float2(va.y, vb.y);
        *reinterpret_cast<float2*>(dst + 4) = make_float2(va.z, vb.z);
        *reinterpret_cast<float2*>(dst + 6) = make_float2(va.w, vb.w);
    }
    __syncwarp();

    // ---- per-edge-pair SH values (packed) ----
    ull H0 = pk2(__ldg(sh0 + ea), __ldg(sh0 + eb));
    float h1xa = __ldg(sh1 + 3 * (size_t)ea + 0), h1xb = __ldg(sh1 + 3 * (size_t)eb + 0);
    float h1ya = __ldg(sh1 + 3 * (size_t)ea + 1), h1yb = __ldg(sh1 + 3 * (size_t)eb + 1);
    float h1za = __ldg(sh1 + 3 * (size_t)ea + 2), h1zb = __ldg(sh1 + 3 * (size_t)eb + 2);
    ull H1X = pk2(h1xa, h1xb), H1Y = pk2(h1ya, h1yb), H1Z = pk2(h1za, h1zb);
    ull NH1X = pk2(-h1xa, -h1xb), NH1Y = pk2(-h1ya, -h1yb), NH1Z = pk2(-h1za, -h1zb);

    // S5[j][k] = sum_a C5[a][j][k] * sh2[a]  (packed over edge pair)
    ull S5[9];
    {
        ull H2[5];
        #pragma unroll
        for (int a = 0; a < 5; a++)
            H2[a] = pk2(__ldg(sh2 + 5 * (size_t)ea + a), __ldg(sh2 + 5 * (size_t)eb + a));
        #pragma unroll
        for (int jk = 0; jk < 9; jk++) {
            ull acc = mul2(pk2(P.c5[jk], P.c5[jk]), H2[0]);
            #pragma unroll
            for (int a = 1; a < 5; a++)
                fma2(acc, pk2(P.c5[a * 9 + jk], P.c5[a * 9 + jk]), H2[a]);
            S5[jk] = acc;
        }
    }

    // ---- packed accumulators: 8 scalar + 8x3 vector outputs ----
    ull MS[8], MV[8][3];
    #pragma unroll
    for (int o = 0; o < 8; o++) {
        MS[o] = 0ull; MV[o][0] = 0ull; MV[o][1] = 0ull; MV[o][2] = 0ull;
    }

    const float* rP = bP + lane * PSTR;

    #pragma unroll
    for (int i = 0; i < 8; i++) {
        // one LDS.64 per feature = ready-made f32x2 (edge a, edge b) operand
        ull F0 = *reinterpret_cast<const ull*>(rP + woff(i));
        ull FX = *reinterpret_cast<const ull*>(rP + woff(8 + 3 * i));
        ull FY = *reinterpret_cast<const ull*>(rP + woff(9 + 3 * i));
        ull FZ = *reinterpret_cast<const ull*>(rP + woff(10 + 3 * i));

        // base quantities (CG norms folded into sW2)
        ull A  = mul2(H0, F0);                               // (0,0,0)
        ull B  = mul2(H1X, FX); fma2(B, H1Y, FY); fma2(B, H1Z, FZ);   // (1,1,0)
        ull P0 = mul2(H0, FX), P1 = mul2(H0, FY), P2 = mul2(H0, FZ);  // (0,1,1)
        ull Q0 = mul2(H1X, F0), Q1 = mul2(H1Y, F0), Q2 = mul2(H1Z, F0); // (1,0,1)
        ull R0 = mul2(H1Y, FZ); fma2(R0, NH1Z, FY);          // (1,1,1) cross
        ull R1 = mul2(H1Z, FX); fma2(R1, NH1X, FZ);
        ull R2 = mul2(H1X, FY); fma2(R2, NH1Y, FX);
        ull U0 = mul2(S5[0], FX); fma2(U0, S5[3], FY); fma2(U0, S5[6], FZ); // (2,1,1)
        ull U1 = mul2(S5[1], FX); fma2(U1, S5[4], FY); fma2(U1, S5[7], FZ);
        ull U2 = mul2(S5[2], FX); fma2(U2, S5[5], FY); fma2(U2, S5[8], FZ);

        const float2* wi = sW2 + i * 48;
        #pragma unroll
        for (int op = 0; op < 4; op++) {
            // one LDS.128 per combo = duplicated weights for o=2op and 2op+1
            ulonglong2 W0 = *reinterpret_cast<const ulonglong2*>(wi + 0 * 8 + 2 * op);
            ulonglong2 W1 = *reinterpret_cast<const ulonglong2*>(wi + 1 * 8 + 2 * op);
            ulonglong2 W2 = *reinterpret_cast<const ulonglong2*>(wi + 2 * 8 + 2 * op);
            ulonglong2 W3 = *reinterpret_cast<const ulonglong2*>(wi + 3 * 8 + 2 * op);
            ulonglong2 W4 = *reinterpret_cast<const ulonglong2*>(wi + 4 * 8 + 2 * op);
            ulonglong2 W5 = *reinterpret_cast<const ulonglong2*>(wi + 5 * 8 + 2 * op);
            int o0 = 2 * op, o1 = 2 * op + 1;
            fma2(MS[o0], W0.x, A); fma2(MS[o0], W3.x, B);
            fma2(MV[o0][0], W1.x, P0); fma2(MV[o0][0], W2.x, Q0);
            fma2(MV[o0][0], W4.x, R0); fma2(MV[o0][0], W5.x, U0);
            fma2(MV[o0][1], W1.x, P1); fma2(MV[o0][1], W2.x, Q1);
            fma2(MV[o0][1], W4.x, R1); fma2(MV[o0][1], W5.x, U1);
            fma2(MV[o0][2], W1.x, P2); fma2(MV[o0][2], W2.x, Q2);
            fma2(MV[o0][2], W4.x, R2); fma2(MV[o0][2], W5.x, U2);
            fma2(MS[o1], W0.y, A); fma2(MS[o1], W3.y, B);
            fma2(MV[o1][0], W1.y, P0); fma2(MV[o1][0], W2.y, Q0);
            fma2(MV[o1][0], W4.y, R0); fma2(MV[o1][0], W5.y, U0);
            fma2(MV[o1][1], W1.y, P1); fma2(MV[o1][1], W2.y, Q1);
            fma2(MV[o1][1], W4.y, R1); fma2(MV[o1][1], W5.y, U1);
            fma2(MV[o1][2], W1.y, P2); fma2(MV[o1][2], W2.y, Q2);
            fma2(MV[o1][2], W4.y, R2); fma2(MV[o1][2], W5.y, U2);
        }
    }
    __syncwarp();   // interleaved staging reads complete before overwrite

    // ---- unpack msg rows into scatter staging (overlays union) ----
    float* bA = uni[warp];
    float* bB = uni[warp] + 32 * ROWF;
    {
        float* wA = bA + lane * ROWF;
        float* wB = bB + lane * ROWF;
        // msg layout: [0..7]=MS, [8+3o+k]=MV[o][k]
        #pragma unroll
        for (int jq = 0; jq < 8; jq++) {
            float4 a4, b4;
            #pragma unroll
            for (int t = 0; t < 4; t++) {
                int j = 4 * jq + t;
                ull m = (j < 8) ? MS[j] : MV[(j - 8) / 3][(j - 8) % 3];
                float2 f = upk2(m);
                (&a4.x)[t] = f.x;
                (&b4.x)[t] = f.y;
            }
            *reinterpret_cast<float4*>(wA + 4 * jq) = a4;
            *reinterpret_cast<float4*>(wB + 4 * jq) = b4;
        }
    }
    __syncwarp();

    // ---- cooperative coalesced scatter: 8 lanes per target row ----
    #pragma unroll
    for (int p = 0; p < 16; p++) {
        int row = (p & 7) * 4 + rsub;          // 0..31
        int er  = (p < 8) ? row : row + 32;    // edge offset within warp
        int tidx = __shfl_sync(FULL, (p < 8) ? ta : tb, row);
        const float* src = ((p < 8) ? bA : bB) + row * ROWF + piece * 4;
        float4 v = *reinterpret_cast<const float4*>(src);
        if (ebase + er < E) {
            float* dst = out + (size_t)tidx * 32 + piece * 4;
            asm volatile("red.global.add.v4.f32 [%0], {%1, %2, %3, %4};"
                         :: "l"(dst), "f"(v.x), "f"(v.y), "f"(v.z), "f"(v.w)
                         : "memory");
        }
    }
}

// ============================================================================
// Launch
// ============================================================================
extern "C" void kernel_launch(void* const* d_in, const int* in_sizes, int n_in,
                              void* d_out, int out_size) {
    const float* node = (const float*)d_in[0];
    const int*   ei   = (const int*)  d_in[1];
    const float* sh0  = (const float*)d_in[2];
    const float* sh1  = (const float*)d_in[3];
    const float* sh2  = (const float*)d_in[4];
    const float* W    = (const float*)d_in[5];
    int E = in_sizes[1] / 2;

    CGParams P;
    float tmp[45];
    hostcg::h_so3(0, 0, 0, tmp); P.k[0] = tmp[0];
    hostcg::h_so3(0, 1, 1, tmp); P.k[1] = tmp[0];
    hostcg::h_so3(1, 0, 1, tmp); P.k[2] = tmp[0];
    hostcg::h_so3(1, 1, 0, tmp); P.k[3] = tmp[0];
    hostcg::h_so3(1, 1, 1, tmp); P.k[4] = tmp[5];
    P.k[5] = 1.0f;
    hostcg::h_so3(2, 1, 1, tmp);
    for (int x = 0; x < 45; x++) P.c5[x] = tmp[x];

    cudaMemsetAsync(d_out, 0, (size_t)out_size * sizeof(float), 0);
    int blocks = (E + 2 * TPB - 1) / (2 * TPB);
    edge_tp_kernel<<<blocks, TPB>>>(node, ei, sh0, sh1, sh2, W, (float*)d_out, E, P);
}

// round 10
// speedup vs baseline: 7.9294x; 1.0943x over previous
#include <cuda_runtime.h>
#include <math.h>

// ============================================================================
// HOST-side CG constant computation (runs in kernel_launch; baked into graph
// as by-value kernel arguments).
// ============================================================================
namespace hostcg {

struct cplx { double re, im; };
static inline cplx cxmul(cplx a, cplx b) {
    cplx r; r.re = a.re * b.re - a.im * b.im; r.im = a.re * b.im + a.im * b.re; return r;
}
static double h_fact(int n) { double r = 1.0; for (int i = 2; i <= n; i++) r *= i; return r; }

static double h_cgc(int j1, int m1, int j2, int m2, int j3, int m3) {
    if (m3 != m1 + m2) return 0.0;
    int vmin = 0;
    if (j2 - j3 - m1 > vmin) vmin = j2 - j3 - m1;
    if (j1 + m2 - j3 > vmin) vmin = j1 + m2 - j3;
    int vmax = j1 + j2 - j3;
    if (j1 - m1 < vmax) vmax = j1 - m1;
    if (j2 + m2 < vmax) vmax = j2 + m2;
    double pref = (2.0 * j3 + 1.0) * h_fact(j3 + j1 - j2) * h_fact(j3 - j1 + j2)
                * h_fact(j1 + j2 - j3) / h_fact(j1 + j2 + j3 + 1);
    pref *= h_fact(j3 + m3) * h_fact(j3 - m3) * h_fact(j1 - m1) * h_fact(j1 + m1)
          * h_fact(j2 - m2) * h_fact(j2 + m2);
    double s = 0.0;
    for (int v = vmin; v <= vmax; v++) {
        double t = 1.0 / (h_fact(v) * h_fact(j1 + j2 - j3 - v) * h_fact(j1 - m1 - v)
                        * h_fact(j2 + m2 - v) * h_fact(j3 - j2 + m1 + v) * h_fact(j3 - j1 - m2 + v));
        s += (v & 1) ? -t : t;
    }
    return sqrt(pref) * s;
}

static void h_qmat(int l, cplx q[5][5]) {
    for (int i = 0; i < 5; i++) for (int j = 0; j < 5; j++) { q[i][j].re = 0.0; q[i][j].im = 0.0; }
    const double is2 = 0.70710678118654752440;
    for (int m = -l; m < 0; m++) {
        q[l + m][l - m].re = is2;
        q[l + m][l + m].im = -is2;
    }
    q[l][l].re = 1.0;
    for (int m = 1; m <= l; m++) {
        double sgn = (m & 1) ? -1.0 : 1.0;
        q[l + m][l + m].re = sgn * is2;
        q[l + m][l - m].im = sgn * is2;
    }
    for (int p = 0; p < l; p++)
        for (int i = 0; i < 5; i++) for (int j = 0; j < 5; j++) {
            double re = q[i][j].re, im = q[i][j].im;
            q[i][j].re = im; q[i][j].im = -re;
        }
}

static void h_so3(int l1, int l2, int l3, float* out) {
    cplx q1[5][5], q2[5][5], q3[5][5];
    h_qmat(l1, q1); h_qmat(l2, q2); h_qmat(l3, q3);
    int d1 = 2 * l1 + 1, d2 = 2 * l2 + 1, d3 = 2 * l3 + 1;
    double C[45];
    double norm = 0.0;
    for (int j = 0; j < d1; j++)
        for (int l = 0; l < d2; l++)
            for (int m = 0; m < d3; m++) {
                double acc = 0.0;
                for (int i = 0; i < d1; i++)
                    for (int k = 0; k < d2; k++) {
                        int n = (i - l1) + (k - l2) + l3;
                        if (n < 0 || n >= d3) continue;
                        double s = h_cgc(l1, i - l1, l2, k - l2, l3, n - l3);
                        if (s == 0.0) continue;
                        cplx t = cxmul(q1[i][j], q2[k][l]);
                        cplx c3; c3.re = q3[n][m].re; c3.im = -q3[n][m].im;
                        t = cxmul(t, c3);
                        acc += t.re * s;
                    }
                C[(j * d2 + l) * d3 + m] = acc;
                norm += acc * acc;
            }
    double inv = 1.0 / sqrt(norm);
    for (int x = 0; x < d1 * d2 * d3; x++) out[x] = (float)(C[x] * inv);
}

} // namespace hostcg

struct CGParams {
    float c5[45];   // (2,1,1) CG, layout [a(5)][j(3)][k(3)]
    float k[6];     // scalar CG coefficient per combo (combo 5 = 1.0)
};

// ============================================================================
// f32x2 helpers: one instruction = 2 fp32 ops (edge-pair packed in lanes)
// ============================================================================
typedef unsigned long long ull;

__device__ __forceinline__ ull pk2(float lo, float hi) {
    ull r; asm("mov.b64 %0, {%1, %2};" : "=l"(r) : "f"(lo), "f"(hi)); return r;
}
__device__ __forceinline__ ull dup2(float v) {
    ull r; asm("mov.b64 %0, {%1, %1};" : "=l"(r) : "f"(v)); return r;
}
__device__ __forceinline__ float2 upk2(ull v) {
    float2 f; asm("mov.b64 {%0, %1}, %2;" : "=f"(f.x), "=f"(f.y) : "l"(v)); return f;
}
__device__ __forceinline__ ull mul2(ull a, ull b) {
    ull r; asm("mul.rn.f32x2 %0, %1, %2;" : "=l"(r) : "l"(a), "l"(b)); return r;
}
__device__ __forceinline__ void fma2(ull& d, ull a, ull b) {
    asm("fma.rn.f32x2 %0, %1, %2, %0;" : "+l"(d) : "l"(a), "l"(b));
}

// ============================================================================
// Staging layout (proven R7): pair-interleaved rows, stride 70, piece swizzle
// f(p)=8p+4(p>>2) — conflict-free for gather STS.64 and feature LDS.64.
// Scatter reuses the union as two 32x36 float4-conflict-free buffers.
// ============================================================================
#define TPB   64              // 2 warps per block
#define NWARP 2
#define PSTR  70              // interleaved row stride (floats)
#define ROWF  36              // scatter staging row stride (floats)
#define UNIF  2304            // union floats/warp

__device__ __forceinline__ constexpr int woff(int c) {
    return 8 * (c >> 2) + 4 * (c >> 4) + 2 * (c & 3);
}

__global__ __launch_bounds__(TPB, 7)
void edge_tp_kernel(const float* __restrict__ node,
                    const int*   __restrict__ ei,
                    const float* __restrict__ sh0,
                    const float* __restrict__ sh1,
                    const float* __restrict__ sh2,
                    const float* __restrict__ W,
                    float*       __restrict__ out,
                    int E, CGParams P) {
    // plain weights [i(8)][combo(6)][o(8)], CG norm folded in (no duplication)
    __shared__ __align__(16) float sW[384];
    // per-warp union: interleaved gather stage OR scatter stage
    __shared__ __align__(16) float uni[NWARP][UNIF];

    for (int x = threadIdx.x; x < 384; x += TPB) {
        int c = x >> 6, i = (x >> 3) & 7, o = x & 7;
        sW[i * 48 + c * 8 + o] = W[x] * P.k[c];
    }
    __syncthreads();

    const unsigned FULL = 0xffffffffu;
    int warp  = threadIdx.x >> 5;
    int lane  = threadIdx.x & 31;
    int piece = lane & 7;      // float4 index within a 32-float row
    int rsub  = lane >> 3;     // row-within-pass (0..3)
    int ebase = (blockIdx.x * NWARP + warp) * 64;
    int ea = ebase + lane;       if (ea >= E) ea = E - 1;
    int eb = ebase + 32 + lane;  if (eb >= E) eb = E - 1;

    int sa = __ldg(ei + ea);
    int sb = __ldg(ei + eb);
    int ta = __ldg(ei + E + ea);
    int tb = __ldg(ei + E + eb);

    float* bP = uni[warp];
    int pieceoff = 8 * piece + 4 * (piece >> 2);   // f(piece)

    // ---- cooperative coalesced gather, pair-interleaved STS.64 ----
    #pragma unroll
    for (int p = 0; p < 8; p++) {
        int er = p * 4 + rsub;
        int ia = __shfl_sync(FULL, sa, er);
        int ib = __shfl_sync(FULL, sb, er);
        float4 va = __ldg(reinterpret_cast<const float4*>(node + (size_t)ia * 32) + piece);
        float4 vb = __ldg(reinterpret_cast<const float4*>(node + (size_t)ib * 32) + piece);
        float* dst = bP + er * PSTR + pieceoff;
        *reinterpret_cast<float2*>(dst + 0) = make_float2(va.x, vb.x);
        *reinterpret_cast<float2*>(dst + 2) = make_float2(va.y, vb.y);
        *reinterpret_cast<float2*>(dst + 4) = make_float2(va.z, vb.z);
        *reinterpret_cast<float2*>(dst + 6) = make_float2(va.w, vb.w);
    }
    __syncwarp();

    // ---- per-edge-pair SH values (packed) ----
    ull H0 = pk2(__ldg(sh0 + ea), __ldg(sh0 + eb));
    float h1xa = __ldg(sh1 + 3 * (size_t)ea + 0), h1xb = __ldg(sh1 + 3 * (size_t)eb + 0);
    float h1ya = __ldg(sh1 + 3 * (size_t)ea + 1), h1yb = __ldg(sh1 + 3 * (size_t)eb + 1);
    float h1za = __ldg(sh1 + 3 * (size_t)ea + 2), h1zb = __ldg(sh1 + 3 * (size_t)eb + 2);
    ull H1X = pk2(h1xa, h1xb), H1Y = pk2(h1ya, h1yb), H1Z = pk2(h1za, h1zb);
    ull NH1X = pk2(-h1xa, -h1xb), NH1Y = pk2(-h1ya, -h1yb), NH1Z = pk2(-h1za, -h1zb);

    // S5[j][k] = sum_a C5[a][j][k] * sh2[a]  (packed over edge pair)
    ull S5[9];
    {
        ull H2[5];
        #pragma unroll
        for (int a = 0; a < 5; a++)
            H2[a] = pk2(__ldg(sh2 + 5 * (size_t)ea + a), __ldg(sh2 + 5 * (size_t)eb + a));
        #pragma unroll
        for (int jk = 0; jk < 9; jk++) {
            ull acc = mul2(dup2(P.c5[jk]), H2[0]);
            #pragma unroll
            for (int a = 1; a < 5; a++)
                fma2(acc, dup2(P.c5[a * 9 + jk]), H2[a]);
            S5[jk] = acc;
        }
    }

    // ---- packed accumulators: 8 scalar + 8x3 vector outputs ----
    ull MS[8], MV[8][3];
    #pragma unroll
    for (int o = 0; o < 8; o++) {
        MS[o] = 0ull; MV[o][0] = 0ull; MV[o][1] = 0ull; MV[o][2] = 0ull;
    }

    const float* rP = bP + lane * PSTR;

    #pragma unroll
    for (int i = 0; i < 8; i++) {
        // one LDS.64 per feature = ready-made f32x2 (edge a, edge b) operand
        ull F0 = *reinterpret_cast<const ull*>(rP + woff(i));
        ull FX = *reinterpret_cast<const ull*>(rP + woff(8 + 3 * i));
        ull FY = *reinterpret_cast<const ull*>(rP + woff(9 + 3 * i));
        ull FZ = *reinterpret_cast<const ull*>(rP + woff(10 + 3 * i));

        // base quantities (CG norms folded into sW)
        ull A  = mul2(H0, F0);                               // (0,0,0)
        ull B  = mul2(H1X, FX); fma2(B, H1Y, FY); fma2(B, H1Z, FZ);   // (1,1,0)
        ull P0 = mul2(H0, FX), P1 = mul2(H0, FY), P2 = mul2(H0, FZ);  // (0,1,1)
        ull Q0 = mul2(H1X, F0), Q1 = mul2(H1Y, F0), Q2 = mul2(H1Z, F0); // (1,0,1)
        ull R0 = mul2(H1Y, FZ); fma2(R0, NH1Z, FY);          // (1,1,1) cross
        ull R1 = mul2(H1Z, FX); fma2(R1, NH1X, FZ);
        ull R2 = mul2(H1X, FY); fma2(R2, NH1Y, FX);
        ull U0 = mul2(S5[0], FX); fma2(U0, S5[3], FY); fma2(U0, S5[6], FZ); // (2,1,1)
        ull U1 = mul2(S5[1], FX); fma2(U1, S5[4], FY); fma2(U1, S5[7], FZ);
        ull U2 = mul2(S5[2], FX); fma2(U2, S5[5], FY); fma2(U2, S5[8], FZ);

        const float* wi = sW + i * 48;
        #pragma unroll
        for (int oh = 0; oh < 2; oh++) {
            // scalar-path combos 0,3: one LDS.128 each (4 plain weights)
            {
                float4 w0 = *reinterpret_cast<const float4*>(wi + 0 * 8 + 4 * oh);
                float4 w3 = *reinterpret_cast<const float4*>(wi + 3 * 8 + 4 * oh);
                #pragma unroll
                for (int r = 0; r < 4; r++) {
                    int o = 4 * oh + r;
                    fma2(MS[o], dup2((&w0.x)[r]), A);
                    fma2(MS[o], dup2((&w3.x)[r]), B);
                }
            }
            // vector-path combos 1,2
            {
                float4 w1 = *reinterpret_cast<const float4*>(wi + 1 * 8 + 4 * oh);
                float4 w2 = *reinterpret_cast<const float4*>(wi + 2 * 8 + 4 * oh);
                #pragma unroll
                for (int r = 0; r < 4; r++) {
                    int o = 4 * oh + r;
                    ull W1 = dup2((&w1.x)[r]), W2 = dup2((&w2.x)[r]);
                    fma2(MV[o][0], W1, P0); fma2(MV[o][0], W2, Q0);
                    fma2(MV[o][1], W1, P1); fma2(MV[o][1], W2, Q1);
                    fma2(MV[o][2], W1, P2); fma2(MV[o][2], W2, Q2);
                }
            }
            // vector-path combos 4,5
            {
                float4 w4 = *reinterpret_cast<const float4*>(wi + 4 * 8 + 4 * oh);
                float4 w5 = *reinterpret_cast<const float4*>(wi + 5 * 8 + 4 * oh);
                #pragma unroll
                for (int r = 0; r < 4; r++) {
                    int o = 4 * oh + r;
                    ull W4 = dup2((&w4.x)[r]), W5 = dup2((&w5.x)[r]);
                    fma2(MV[o][0], W4, R0); fma2(MV[o][0], W5, U0);
                    fma2(MV[o][1], W4, R1); fma2(MV[o][1], W5, U1);
                    fma2(MV[o][2], W4, R2); fma2(MV[o][2], W5, U2);
                }
            }
        }
    }
    __syncwarp();   // interleaved staging reads complete before overwrite

    // ---- unpack msg rows into scatter staging (overlays union) ----
    float* bA = uni[warp];
    float* bB = uni[warp] + 32 * ROWF;
    {
        float* wA = bA + lane * ROWF;
        float* wB = bB + lane * ROWF;
        // msg layout: [0..7]=MS, [8+3o+k]=MV[o][k]
        #pragma unroll
        for (int jq = 0; jq < 8; jq++) {
            float4 a4, b4;
            #pragma unroll
            for (int t = 0; t < 4; t++) {
                int j = 4 * jq + t;
                ull m = (j < 8) ? MS[j] : MV[(j - 8) / 3][(j - 8) % 3];
                float2 f = upk2(m);
                (&a4.x)[t] = f.x;
                (&b4.x)[t] = f.y;
            }
            *reinterpret_cast<float4*>(wA + 4 * jq) = a4;
            *reinterpret_cast<float4*>(wB + 4 * jq) = b4;
        }
    }
    __syncwarp();

    // ---- cooperative coalesced scatter: 8 lanes per target row ----
    #pragma unroll
    for (int p = 0; p < 16; p++) {
        int row = (p & 7) * 4 + rsub;          // 0..31
        int er  = (p < 8) ? row : row + 32;    // edge offset within warp
        int tidx = __shfl_sync(FULL, (p < 8) ? ta : tb, row);
        const float* src = ((p < 8) ? bA : bB) + row * ROWF + piece * 4;
        float4 v = *reinterpret_cast<const float4*>(src);
        if (ebase + er < E) {
            float* dst = out + (size_t)tidx * 32 + piece * 4;
            asm volatile("red.global.add.v4.f32 [%0], {%1, %2, %3, %4};"
                         :: "l"(dst), "f"(v.x), "f"(v.y), "f"(v.z), "f"(v.w)
                         : "memory");
        }
    }
}

// ============================================================================
// Launch
// ============================================================================
extern "C" void kernel_launch(void* const* d_in, const int* in_sizes, int n_in,
                              void* d_out, int out_size) {
    const float* node = (const float*)d_in[0];
    const int*   ei   = (const int*)  d_in[1];
    const float* sh0  = (const float*)d_in[2];
    const float* sh1  = (const float*)d_in[3];
    const float* sh2  = (const float*)d_in[4];
    const float* W    = (const float*)d_in[5];
    int E = in_sizes[1] / 2;

    CGParams P;
    float tmp[45];
    hostcg::h_so3(0, 0, 0, tmp); P.k[0] = tmp[0];
    hostcg::h_so3(0, 1, 1, tmp); P.k[1] = tmp[0];
    hostcg::h_so3(1, 0, 1, tmp); P.k[2] = tmp[0];
    hostcg::h_so3(1, 1, 0, tmp); P.k[3] = tmp[0];
    hostcg::h_so3(1, 1, 1, tmp); P.k[4] = tmp[5];
    P.k[5] = 1.0f;
    hostcg::h_so3(2, 1, 1, tmp);
    for (int x = 0; x < 45; x++) P.c5[x] = tmp[x];

    cudaMemsetAsync(d_out, 0, (size_t)out_size * sizeof(float), 0);
    int blocks = (E + 2 * TPB - 1) / (2 * TPB);
    edge_tp_kernel<<<blocks, TPB>>>(node, ei, sh0, sh1, sh2, W, (float*)d_out, E, P);
}

// round 11
// speedup vs baseline: 9.1667x; 1.1560x over previous
#include <cuda_runtime.h>
#include <math.h>

// ============================================================================
// HOST-side CG constant computation (runs in kernel_launch; baked into graph
// as by-value kernel arguments).
// ============================================================================
namespace hostcg {

struct cplx { double re, im; };
static inline cplx cxmul(cplx a, cplx b) {
    cplx r; r.re = a.re * b.re - a.im * b.im; r.im = a.re * b.im + a.im * b.re; return r;
}
static double h_fact(int n) { double r = 1.0; for (int i = 2; i <= n; i++) r *= i; return r; }

static double h_cgc(int j1, int m1, int j2, int m2, int j3, int m3) {
    if (m3 != m1 + m2) return 0.0;
    int vmin = 0;
    if (j2 - j3 - m1 > vmin) vmin = j2 - j3 - m1;
    if (j1 + m2 - j3 > vmin) vmin = j1 + m2 - j3;
    int vmax = j1 + j2 - j3;
    if (j1 - m1 < vmax) vmax = j1 - m1;
    if (j2 + m2 < vmax) vmax = j2 + m2;
    double pref = (2.0 * j3 + 1.0) * h_fact(j3 + j1 - j2) * h_fact(j3 - j1 + j2)
                * h_fact(j1 + j2 - j3) / h_fact(j1 + j2 + j3 + 1);
    pref *= h_fact(j3 + m3) * h_fact(j3 - m3) * h_fact(j1 - m1) * h_fact(j1 + m1)
          * h_fact(j2 - m2) * h_fact(j2 + m2);
    double s = 0.0;
    for (int v = vmin; v <= vmax; v++) {
        double t = 1.0 / (h_fact(v) * h_fact(j1 + j2 - j3 - v) * h_fact(j1 - m1 - v)
                        * h_fact(j2 + m2 - v) * h_fact(j3 - j2 + m1 + v) * h_fact(j3 - j1 - m2 + v));
        s += (v & 1) ? -t : t;
    }
    return sqrt(pref) * s;
}

static void h_qmat(int l, cplx q[5][5]) {
    for (int i = 0; i < 5; i++) for (int j = 0; j < 5; j++) { q[i][j].re = 0.0; q[i][j].im = 0.0; }
    const double is2 = 0.70710678118654752440;
    for (int m = -l; m < 0; m++) {
        q[l + m][l - m].re = is2;
        q[l + m][l + m].im = -is2;
    }
    q[l][l].re = 1.0;
    for (int m = 1; m <= l; m++) {
        double sgn = (m & 1) ? -1.0 : 1.0;
        q[l + m][l + m].re = sgn * is2;
        q[l + m][l - m].im = sgn * is2;
    }
    for (int p = 0; p < l; p++)
        for (int i = 0; i < 5; i++) for (int j = 0; j < 5; j++) {
            double re = q[i][j].re, im = q[i][j].im;
            q[i][j].re = im; q[i][j].im = -re;
        }
}

static void h_so3(int l1, int l2, int l3, float* out) {
    cplx q1[5][5], q2[5][5], q3[5][5];
    h_qmat(l1, q1); h_qmat(l2, q2); h_qmat(l3, q3);
    int d1 = 2 * l1 + 1, d2 = 2 * l2 + 1, d3 = 2 * l3 + 1;
    double C[45];
    double norm = 0.0;
    for (int j = 0; j < d1; j++)
        for (int l = 0; l < d2; l++)
            for (int m = 0; m < d3; m++) {
                double acc = 0.0;
                for (int i = 0; i < d1; i++)
                    for (int k = 0; k < d2; k++) {
                        int n = (i - l1) + (k - l2) + l3;
                        if (n < 0 || n >= d3) continue;
                        double s = h_cgc(l1, i - l1, l2, k - l2, l3, n - l3);
                        if (s == 0.0) continue;
                        cplx t = cxmul(q1[i][j], q2[k][l]);
                        cplx c3; c3.re = q3[n][m].re; c3.im = -q3[n][m].im;
                        t = cxmul(t, c3);
                        acc += t.re * s;
                    }
                C[(j * d2 + l) * d3 + m] = acc;
                norm += acc * acc;
            }
    double inv = 1.0 / sqrt(norm);
    for (int x = 0; x < d1 * d2 * d3; x++) out[x] = (float)(C[x] * inv);
}

} // namespace hostcg

struct CGParams {
    float c5[45];   // (2,1,1) CG, layout [a(5)][j(3)][k(3)]
    float k[6];     // scalar CG coefficient per combo (combo 5 = 1.0)
};

// Raw weights [combo(6)][i(8)][o(8)] in constant memory — filled by a
// graph-capturable device-to-device cudaMemcpyToSymbolAsync each launch.
// Warp-uniform accesses go through the constant-cache port, NOT L1tex.
__constant__ float cW[384];

// ============================================================================
// f32x2 helpers: one instruction = 2 fp32 ops (edge-pair packed in lanes)
// ============================================================================
typedef unsigned long long ull;

__device__ __forceinline__ ull pk2(float lo, float hi) {
    ull r; asm("mov.b64 %0, {%1, %2};" : "=l"(r) : "f"(lo), "f"(hi)); return r;
}
__device__ __forceinline__ ull dup2(float v) {
    ull r; asm("mov.b64 %0, {%1, %1};" : "=l"(r) : "f"(v)); return r;
}
__device__ __forceinline__ float2 upk2(ull v) {
    float2 f; asm("mov.b64 {%0, %1}, %2;" : "=f"(f.x), "=f"(f.y) : "l"(v)); return f;
}
__device__ __forceinline__ ull mul2(ull a, ull b) {
    ull r; asm("mul.rn.f32x2 %0, %1, %2;" : "=l"(r) : "l"(a), "l"(b)); return r;
}
__device__ __forceinline__ void fma2(ull& d, ull a, ull b) {
    asm("fma.rn.f32x2 %0, %1, %2, %0;" : "+l"(d) : "l"(a), "l"(b));
}

// ============================================================================
// Staging layout (proven): pair-interleaved rows, stride 70, piece swizzle
// f(p)=8p+4(p>>2) — conflict-free for gather STS.64 and feature LDS.64.
// Scatter reuses the union as two 32x36 float4-conflict-free buffers.
// ============================================================================
#define TPB   64              // 2 warps per block
#define NWARP 2
#define PSTR  70              // interleaved row stride (floats)
#define ROWF  36              // scatter staging row stride (floats)
#define UNIF  2304            // union floats/warp

__device__ __forceinline__ constexpr int woff(int c) {
    return 8 * (c >> 2) + 4 * (c >> 4) + 2 * (c & 3);
}

__global__ __launch_bounds__(TPB, 7)
void edge_tp_kernel(const float* __restrict__ node,
                    const int*   __restrict__ ei,
                    const float* __restrict__ sh0,
                    const float* __restrict__ sh1,
                    const float* __restrict__ sh2,
                    float*       __restrict__ out,
                    int E, CGParams P) {
    // per-warp union: interleaved gather stage OR scatter stage
    __shared__ __align__(16) float uni[NWARP][UNIF];

    const unsigned FULL = 0xffffffffu;
    int warp  = threadIdx.x >> 5;
    int lane  = threadIdx.x & 31;
    int piece = lane & 7;      // float4 index within a 32-float row
    int rsub  = lane >> 3;     // row-within-pass (0..3)
    int ebase = (blockIdx.x * NWARP + warp) * 64;
    int ea = ebase + lane;       if (ea >= E) ea = E - 1;
    int eb = ebase + 32 + lane;  if (eb >= E) eb = E - 1;

    int sa = __ldg(ei + ea);
    int sb = __ldg(ei + eb);
    int ta = __ldg(ei + E + ea);
    int tb = __ldg(ei + E + eb);

    float* bP = uni[warp];
    int pieceoff = 8 * piece + 4 * (piece >> 2);   // f(piece)

    // ---- cooperative coalesced gather, pair-interleaved STS.64 ----
    #pragma unroll
    for (int p = 0; p < 8; p++) {
        int er = p * 4 + rsub;
        int ia = __shfl_sync(FULL, sa, er);
        int ib = __shfl_sync(FULL, sb, er);
        float4 va = __ldg(reinterpret_cast<const float4*>(node + (size_t)ia * 32) + piece);
        float4 vb = __ldg(reinterpret_cast<const float4*>(node + (size_t)ib * 32) + piece);
        float* dst = bP + er * PSTR + pieceoff;
        *reinterpret_cast<float2*>(dst + 0) = make_float2(va.x, vb.x);
        *reinterpret_cast<float2*>(dst + 2) = make_float2(va.y, vb.y);
        *reinterpret_cast<float2*>(dst + 4) = make_float2(va.z, vb.z);
        *reinterpret_cast<float2*>(dst + 6) = make_float2(va.w, vb.w);
    }
    __syncwarp();

    // ---- per-edge-pair SH values, CG norms k[c] pre-folded into SH regs ----
    // (weights in cW are RAW; products identical to folding k into weights)
    float k0 = P.k[0], k1 = P.k[1], k2 = P.k[2], k3 = P.k[3], k4 = P.k[4];
    float h0a = __ldg(sh0 + ea),               h0b = __ldg(sh0 + eb);
    float h1xa = __ldg(sh1 + 3 * (size_t)ea + 0), h1xb = __ldg(sh1 + 3 * (size_t)eb + 0);
    float h1ya = __ldg(sh1 + 3 * (size_t)ea + 1), h1yb = __ldg(sh1 + 3 * (size_t)eb + 1);
    float h1za = __ldg(sh1 + 3 * (size_t)ea + 2), h1zb = __ldg(sh1 + 3 * (size_t)eb + 2);

    ull H0K0 = pk2(h0a * k0, h0b * k0);                 // combo (0,0,0)
    ull H0K1 = pk2(h0a * k1, h0b * k1);                 // combo (0,1,1)
    ull H1XK2 = pk2(h1xa * k2, h1xb * k2);              // combo (1,0,1)
    ull H1YK2 = pk2(h1ya * k2, h1yb * k2);
    ull H1ZK2 = pk2(h1za * k2, h1zb * k2);
    ull H1XK3 = pk2(h1xa * k3, h1xb * k3);              // combo (1,1,0)
    ull H1YK3 = pk2(h1ya * k3, h1yb * k3);
    ull H1ZK3 = pk2(h1za * k3, h1zb * k3);
    ull H1XK4 = pk2(h1xa * k4, h1xb * k4);              // combo (1,1,1)
    ull H1YK4 = pk2(h1ya * k4, h1yb * k4);
    ull H1ZK4 = pk2(h1za * k4, h1zb * k4);
    ull NH1XK4 = pk2(-h1xa * k4, -h1xb * k4);
    ull NH1YK4 = pk2(-h1ya * k4, -h1yb * k4);
    ull NH1ZK4 = pk2(-h1za * k4, -h1zb * k4);

    // S5[j][k] = sum_a C5[a][j][k] * sh2[a]  (packed over edge pair, k5=1)
    ull S5[9];
    {
        ull H2[5];
        #pragma unroll
        for (int a = 0; a < 5; a++)
            H2[a] = pk2(__ldg(sh2 + 5 * (size_t)ea + a), __ldg(sh2 + 5 * (size_t)eb + a));
        #pragma unroll
        for (int jk = 0; jk < 9; jk++) {
            ull acc = mul2(dup2(P.c5[jk]), H2[0]);
            #pragma unroll
            for (int a = 1; a < 5; a++)
                fma2(acc, dup2(P.c5[a * 9 + jk]), H2[a]);
            S5[jk] = acc;
        }
    }

    // ---- packed accumulators: 8 scalar + 8x3 vector outputs ----
    ull MS[8], MV[8][3];
    #pragma unroll
    for (int o = 0; o < 8; o++) {
        MS[o] = 0ull; MV[o][0] = 0ull; MV[o][1] = 0ull; MV[o][2] = 0ull;
    }

    const float* rP = bP + lane * PSTR;

    #pragma unroll
    for (int i = 0; i < 8; i++) {
        // one LDS.64 per feature = ready-made f32x2 (edge a, edge b) operand
        ull F0 = *reinterpret_cast<const ull*>(rP + woff(i));
        ull FX = *reinterpret_cast<const ull*>(rP + woff(8 + 3 * i));
        ull FY = *reinterpret_cast<const ull*>(rP + woff(9 + 3 * i));
        ull FZ = *reinterpret_cast<const ull*>(rP + woff(10 + 3 * i));

        // base quantities (CG norms pre-folded into the H-regs)
        ull A  = mul2(H0K0, F0);                                        // (0,0,0)
        ull B  = mul2(H1XK3, FX); fma2(B, H1YK3, FY); fma2(B, H1ZK3, FZ); // (1,1,0)
        ull P0 = mul2(H0K1, FX), P1 = mul2(H0K1, FY), P2 = mul2(H0K1, FZ); // (0,1,1)
        ull Q0 = mul2(H1XK2, F0), Q1 = mul2(H1YK2, F0), Q2 = mul2(H1ZK2, F0); // (1,0,1)
        ull R0 = mul2(H1YK4, FZ); fma2(R0, NH1ZK4, FY);                 // (1,1,1)
        ull R1 = mul2(H1ZK4, FX); fma2(R1, NH1XK4, FZ);
        ull R2 = mul2(H1XK4, FY); fma2(R2, NH1YK4, FX);
        ull U0 = mul2(S5[0], FX); fma2(U0, S5[3], FY); fma2(U0, S5[6], FZ); // (2,1,1)
        ull U1 = mul2(S5[1], FX); fma2(U1, S5[4], FY); fma2(U1, S5[7], FZ);
        ull U2 = mul2(S5[2], FX); fma2(U2, S5[5], FY); fma2(U2, S5[8], FZ);

        #pragma unroll
        for (int oh = 0; oh < 2; oh++) {
            // weight fetches: LDC.128 from constant cache (NOT L1tex)
            // cW layout raw [combo(6)][i(8)][o(8)]
            {
                float4 w0 = *reinterpret_cast<const float4*>(cW + 0 * 64 + i * 8 + 4 * oh);
                float4 w3 = *reinterpret_cast<const float4*>(cW + 3 * 64 + i * 8 + 4 * oh);
                #pragma unroll
                for (int r = 0; r < 4; r++) {
                    int o = 4 * oh + r;
                    fma2(MS[o], dup2((&w0.x)[r]), A);
                    fma2(MS[o], dup2((&w3.x)[r]), B);
                }
            }
            {
                float4 w1 = *reinterpret_cast<const float4*>(cW + 1 * 64 + i * 8 + 4 * oh);
                float4 w2 = *reinterpret_cast<const float4*>(cW + 2 * 64 + i * 8 + 4 * oh);
                #pragma unroll
                for (int r = 0; r < 4; r++) {
                    int o = 4 * oh + r;
                    ull W1 = dup2((&w1.x)[r]), W2 = dup2((&w2.x)[r]);
                    fma2(MV[o][0], W1, P0); fma2(MV[o][0], W2, Q0);
                    fma2(MV[o][1], W1, P1); fma2(MV[o][1], W2, Q1);
                    fma2(MV[o][2], W1, P2); fma2(MV[o][2], W2, Q2);
                }
            }
            {
                float4 w4 = *reinterpret_cast<const float4*>(cW + 4 * 64 + i * 8 + 4 * oh);
                float4 w5 = *reinterpret_cast<const float4*>(cW + 5 * 64 + i * 8 + 4 * oh);
                #pragma unroll
                for (int r = 0; r < 4; r++) {
                    int o = 4 * oh + r;
                    ull W4 = dup2((&w4.x)[r]), W5 = dup2((&w5.x)[r]);
                    fma2(MV[o][0], W4, R0); fma2(MV[o][0], W5, U0);
                    fma2(MV[o][1], W4, R1); fma2(MV[o][1], W5, U1);
                    fma2(MV[o][2], W4, R2); fma2(MV[o][2], W5, U2);
                }
            }
        }
    }
    __syncwarp();   // interleaved staging reads complete before overwrite

    // ---- unpack msg rows into scatter staging (overlays union) ----
    float* bA = uni[warp];
    float* bB = uni[warp] + 32 * ROWF;
    {
        float* wA = bA + lane * ROWF;
        float* wB = bB + lane * ROWF;
        // msg layout: [0..7]=MS, [8+3o+k]=MV[o][k]
        #pragma unroll
        for (int jq = 0; jq < 8; jq++) {
            float4 a4, b4;
            #pragma unroll
            for (int t = 0; t < 4; t++) {
                int j = 4 * jq + t;
                ull m = (j < 8) ? MS[j] : MV[(j - 8) / 3][(j - 8) % 3];
                float2 f = upk2(m);
                (&a4.x)[t] = f.x;
                (&b4.x)[t] = f.y;
            }
            *reinterpret_cast<float4*>(wA + 4 * jq) = a4;
            *reinterpret_cast<float4*>(wB + 4 * jq) = b4;
        }
    }
    __syncwarp();

    // ---- cooperative coalesced scatter: 8 lanes per target row ----
    #pragma unroll
    for (int p = 0; p < 16; p++) {
        int row = (p & 7) * 4 + rsub;          // 0..31
        int er  = (p < 8) ? row : row + 32;    // edge offset within warp
        int tidx = __shfl_sync(FULL, (p < 8) ? ta : tb, row);
        const float* src = ((p < 8) ? bA : bB) + row * ROWF + piece * 4;
        float4 v = *reinterpret_cast<const float4*>(src);
        if (ebase + er < E) {
            float* dst = out + (size_t)tidx * 32 + piece * 4;
            asm volatile("red.global.add.v4.f32 [%0], {%1, %2, %3, %4};"
                         :: "l"(dst), "f"(v.x), "f"(v.y), "f"(v.z), "f"(v.w)
                         : "memory");
        }
    }
}

// ============================================================================
// Launch: D2D copy of W into __constant__ (capturable memcpy node),
// memset output, one edge kernel. No allocations, no syncs.
// ============================================================================
extern "C" void kernel_launch(void* const* d_in, const int* in_sizes, int n_in,
                              void* d_out, int out_size) {
    const float* node = (const float*)d_in[0];
    const int*   ei   = (const int*)  d_in[1];
    const float* sh0  = (const float*)d_in[2];
    const float* sh1  = (const float*)d_in[3];
    const float* sh2  = (const float*)d_in[4];
    const float* W    = (const float*)d_in[5];
    int E = in_sizes[1] / 2;

    CGParams P;
    float tmp[45];
    hostcg::h_so3(0, 0, 0, tmp); P.k[0] = tmp[0];
    hostcg::h_so3(0, 1, 1, tmp); P.k[1] = tmp[0];
    hostcg::h_so3(1, 0, 1, tmp); P.k[2] = tmp[0];
    hostcg::h_so3(1, 1, 0, tmp); P.k[3] = tmp[0];
    hostcg::h_so3(1, 1, 1, tmp); P.k[4] = tmp[5];
    P.k[5] = 1.0f;
    hostcg::h_so3(2, 1, 1, tmp);
    for (int x = 0; x < 45; x++) P.c5[x] = tmp[x];

    cudaMemcpyToSymbolAsync(cW, W, 384 * sizeof(float), 0,
                            cudaMemcpyDeviceToDevice, 0);
    cudaMemsetAsync(d_out, 0, (size_t)out_size * sizeof(float), 0);
    int blocks = (E + 2 * TPB - 1) / (2 * TPB);
    edge_tp_kernel<<<blocks, TPB>>>(node, ei, sh0, sh1, sh2, (float*)d_out, E, P);
}

// round 17
// speedup vs baseline: 9.3425x; 1.0192x over previous
#include <cuda_runtime.h>
#include <math.h>

// ============================================================================
// HOST-side CG constant computation (runs in kernel_launch; baked into graph
// as by-value kernel arguments).
// ============================================================================
namespace hostcg {

struct cplx { double re, im; };
static inline cplx cxmul(cplx a, cplx b) {
    cplx r; r.re = a.re * b.re - a.im * b.im; r.im = a.re * b.im + a.im * b.re; return r;
}
static double h_fact(int n) { double r = 1.0; for (int i = 2; i <= n; i++) r *= i; return r; }

static double h_cgc(int j1, int m1, int j2, int m2, int j3, int m3) {
    if (m3 != m1 + m2) return 0.0;
    int vmin = 0;
    if (j2 - j3 - m1 > vmin) vmin = j2 - j3 - m1;
    if (j1 + m2 - j3 > vmin) vmin = j1 + m2 - j3;
    int vmax = j1 + j2 - j3;
    if (j1 - m1 < vmax) vmax = j1 - m1;
    if (j2 + m2 < vmax) vmax = j2 + m2;
    double pref = (2.0 * j3 + 1.0) * h_fact(j3 + j1 - j2) * h_fact(j3 - j1 + j2)
                * h_fact(j1 + j2 - j3) / h_fact(j1 + j2 + j3 + 1);
    pref *= h_fact(j3 + m3) * h_fact(j3 - m3) * h_fact(j1 - m1) * h_fact(j1 + m1)
          * h_fact(j2 - m2) * h_fact(j2 + m2);
    double s = 0.0;
    for (int v = vmin; v <= vmax; v++) {
        double t = 1.0 / (h_fact(v) * h_fact(j1 + j2 - j3 - v) * h_fact(j1 - m1 - v)
                        * h_fact(j2 + m2 - v) * h_fact(j3 - j2 + m1 + v) * h_fact(j3 - j1 - m2 + v));
        s += (v & 1) ? -t : t;
    }
    return sqrt(pref) * s;
}

static void h_qmat(int l, cplx q[5][5]) {
    for (int i = 0; i < 5; i++) for (int j = 0; j < 5; j++) { q[i][j].re = 0.0; q[i][j].im = 0.0; }
    const double is2 = 0.70710678118654752440;
    for (int m = -l; m < 0; m++) {
        q[l + m][l - m].re = is2;
        q[l + m][l + m].im = -is2;
    }
    q[l][l].re = 1.0;
    for (int m = 1; m <= l; m++) {
        double sgn = (m & 1) ? -1.0 : 1.0;
        q[l + m][l + m].re = sgn * is2;
        q[l + m][l - m].im = sgn * is2;
    }
    for (int p = 0; p < l; p++)
        for (int i = 0; i < 5; i++) for (int j = 0; j < 5; j++) {
            double re = q[i][j].re, im = q[i][j].im;
            q[i][j].re = im; q[i][j].im = -re;
        }
}

static void h_so3(int l1, int l2, int l3, float* out) {
    cplx q1[5][5], q2[5][5], q3[5][5];
    h_qmat(l1, q1); h_qmat(l2, q2); h_qmat(l3, q3);
    int d1 = 2 * l1 + 1, d2 = 2 * l2 + 1, d3 = 2 * l3 + 1;
    double C[45];
    double norm = 0.0;
    for (int j = 0; j < d1; j++)
        for (int l = 0; l < d2; l++)
            for (int m = 0; m < d3; m++) {
                double acc = 0.0;
                for (int i = 0; i < d1; i++)
                    for (int k = 0; k < d2; k++) {
                        int n = (i - l1) + (k - l2) + l3;
                        if (n < 0 || n >= d3) continue;
                        double s = h_cgc(l1, i - l1, l2, k - l2, l3, n - l3);
                        if (s == 0.0) continue;
                        cplx t = cxmul(q1[i][j], q2[k][l]);
                        cplx c3; c3.re = q3[n][m].re; c3.im = -q3[n][m].im;
                        t = cxmul(t, c3);
                        acc += t.re * s;
                    }
                C[(j * d2 + l) * d3 + m] = acc;
                norm += acc * acc;
            }
    double inv = 1.0 / sqrt(norm);
    for (int x = 0; x < d1 * d2 * d3; x++) out[x] = (float)(C[x] * inv);
}

} // namespace hostcg

struct CGParams {
    float c5[45];   // (2,1,1) CG, layout [a(5)][j(3)][k(3)]
    float k[6];     // scalar CG coefficient per combo (combo 5 = 1.0)
};

// Duplicated, k-folded weights in constant memory.
// Layout: float2[((i*2+oh)*6+c)*4+r] = (w,w) with w = W[c][i][4*oh+r]*k[c].
// Filled each launch by dup_kernel -> g_Wdup -> D2D memcpyToSymbol (capturable).
__constant__ float2 cWd[384];
__device__  float2 g_Wdup[384];

__global__ void dup_kernel(const float* __restrict__ W, CGParams P) {
    int x = threadIdx.x;                 // 384 threads
    int c = x >> 6, i = (x >> 3) & 7, o = x & 7;
    int oh = o >> 2, r = o & 3;
    float w = W[x] * P.k[c];
    g_Wdup[((i * 2 + oh) * 6 + c) * 4 + r] = make_float2(w, w);
}

// ============================================================================
// f32x2 helpers: one instruction = 2 fp32 ops (edge-pair packed in lanes)
// ============================================================================
typedef unsigned long long ull;

__device__ __forceinline__ ull pk2(float lo, float hi) {
    ull r; asm("mov.b64 %0, {%1, %2};" : "=l"(r) : "f"(lo), "f"(hi)); return r;
}
__device__ __forceinline__ ull dup2(float v) {
    ull r; asm("mov.b64 %0, {%1, %1};" : "=l"(r) : "f"(v)); return r;
}
__device__ __forceinline__ float2 upk2(ull v) {
    float2 f; asm("mov.b64 {%0, %1}, %2;" : "=f"(f.x), "=f"(f.y) : "l"(v)); return f;
}
__device__ __forceinline__ ull mul2(ull a, ull b) {
    ull r; asm("mul.rn.f32x2 %0, %1, %2;" : "=l"(r) : "l"(a), "l"(b)); return r;
}
__device__ __forceinline__ void fma2(ull& d, ull a, ull b) {
    asm("fma.rn.f32x2 %0, %1, %2, %0;" : "+l"(d) : "l"(a), "l"(b));
}

// ============================================================================
// Staging layout (proven): pair-interleaved rows, stride 70, piece swizzle
// f(p)=8p+4(p>>2) — conflict-free for gather STS.64 and feature LDS.64.
// Scatter reuses the union as two 32x36 float4-conflict-free buffers.
// ============================================================================
#define TPB   64              // 2 warps per block
#define NWARP 2
#define PSTR  70              // interleaved row stride (floats)
#define ROWF  36              // scatter staging row stride (floats)
#define UNIF  2304            // union floats/warp

__device__ __forceinline__ constexpr int woff(int c) {
    return 8 * (c >> 2) + 4 * (c >> 4) + 2 * (c & 3);
}

__global__ __launch_bounds__(TPB, 8)
void edge_tp_kernel(const float* __restrict__ node,
                    const int*   __restrict__ ei,
                    const float* __restrict__ sh0,
                    const float* __restrict__ sh1,
                    const float* __restrict__ sh2,
                    float*       __restrict__ out,
                    int E, CGParams P) {
    // per-warp union: interleaved gather stage OR scatter stage
    __shared__ __align__(16) float uni[NWARP][UNIF];

    const unsigned FULL = 0xffffffffu;
    int warp  = threadIdx.x >> 5;
    int lane  = threadIdx.x & 31;
    int piece = lane & 7;      // float4 index within a 32-float row
    int rsub  = lane >> 3;     // row-within-pass (0..3)
    int ebase = (blockIdx.x * NWARP + warp) * 64;
    int ea = ebase + lane;       if (ea >= E) ea = E - 1;
    int eb = ebase + 32 + lane;  if (eb >= E) eb = E - 1;

    int sa = __ldg(ei + ea);
    int sb = __ldg(ei + eb);
    int ta = __ldg(ei + E + ea);
    int tb = __ldg(ei + E + eb);

    float* bP = uni[warp];
    int pieceoff = 8 * piece + 4 * (piece >> 2);   // f(piece)

    // ---- cooperative coalesced gather, pair-interleaved STS.64 ----
    #pragma unroll
    for (int p = 0; p < 8; p++) {
        int er = p * 4 + rsub;
        int ia = __shfl_sync(FULL, sa, er);
        int ib = __shfl_sync(FULL, sb, er);
        float4 va = __ldg(reinterpret_cast<const float4*>(node + (size_t)ia * 32) + piece);
        float4 vb = __ldg(reinterpret_cast<const float4*>(node + (size_t)ib * 32) + piece);
        float* dst = bP + er * PSTR + pieceoff;
        *reinterpret_cast<float2*>(dst + 0) = make_float2(va.x, vb.x);
        *reinterpret_cast<float2*>(dst + 2) = make_float2(va.y, vb.y);
        *reinterpret_cast<float2*>(dst + 4) = make_float2(va.z, vb.z);
        *reinterpret_cast<float2*>(dst + 6) = make_float2(va.w, vb.w);
    }
    __syncwarp();

    // ---- per-edge-pair SH values (plain; CG norms folded into cWd) ----
    float h0a = __ldg(sh0 + ea),                  h0b = __ldg(sh0 + eb);
    float h1xa = __ldg(sh1 + 3 * (size_t)ea + 0), h1xb = __ldg(sh1 + 3 * (size_t)eb + 0);
    float h1ya = __ldg(sh1 + 3 * (size_t)ea + 1), h1yb = __ldg(sh1 + 3 * (size_t)eb + 1);
    float h1za = __ldg(sh1 + 3 * (size_t)ea + 2), h1zb = __ldg(sh1 + 3 * (size_t)eb + 2);

    ull H0  = pk2(h0a, h0b);
    ull H1X = pk2(h1xa, h1xb), H1Y = pk2(h1ya, h1yb), H1Z = pk2(h1za, h1zb);
    ull NH1X = pk2(-h1xa, -h1xb), NH1Y = pk2(-h1ya, -h1yb), NH1Z = pk2(-h1za, -h1zb);

    // S5[j][k] = sum_a C5[a][j][k] * sh2[a]  (packed over edge pair, k5=1)
    ull S5[9];
    {
        ull H2[5];
        #pragma unroll
        for (int a = 0; a < 5; a++)
            H2[a] = pk2(__ldg(sh2 + 5 * (size_t)ea + a), __ldg(sh2 + 5 * (size_t)eb + a));
        #pragma unroll
        for (int jk = 0; jk < 9; jk++) {
            ull acc = mul2(dup2(P.c5[jk]), H2[0]);
            #pragma unroll
            for (int a = 1; a < 5; a++)
                fma2(acc, dup2(P.c5[a * 9 + jk]), H2[a]);
            S5[jk] = acc;
        }
    }

    // ---- packed accumulators: 8 scalar + 8x3 vector outputs ----
    ull MS[8], MV[8][3];
    #pragma unroll
    for (int o = 0; o < 8; o++) {
        MS[o] = 0ull; MV[o][0] = 0ull; MV[o][1] = 0ull; MV[o][2] = 0ull;
    }

    const float* rP = bP + lane * PSTR;
    const ulonglong2* wdt = reinterpret_cast<const ulonglong2*>(cWd);

    #pragma unroll
    for (int i = 0; i < 8; i++) {
        // one LDS.64 per feature = ready-made f32x2 (edge a, edge b) operand
        ull F0 = *reinterpret_cast<const ull*>(rP + woff(i));
        ull FX = *reinterpret_cast<const ull*>(rP + woff(8 + 3 * i));
        ull FY = *reinterpret_cast<const ull*>(rP + woff(9 + 3 * i));
        ull FZ = *reinterpret_cast<const ull*>(rP + woff(10 + 3 * i));

        // base quantities (CG norms live in the weights)
        ull A  = mul2(H0, F0);                                    // (0,0,0)
        ull B  = mul2(H1X, FX); fma2(B, H1Y, FY); fma2(B, H1Z, FZ); // (1,1,0)
        ull P0 = mul2(H0, FX), P1 = mul2(H0, FY), P2 = mul2(H0, FZ); // (0,1,1)
        ull Q0 = mul2(H1X, F0), Q1 = mul2(H1Y, F0), Q2 = mul2(H1Z, F0); // (1,0,1)
        ull R0 = mul2(H1Y, FZ); fma2(R0, NH1Z, FY);               // (1,1,1)
        ull R1 = mul2(H1Z, FX); fma2(R1, NH1X, FZ);
        ull R2 = mul2(H1X, FY); fma2(R2, NH1Y, FX);
        ull U0 = mul2(S5[0], FX); fma2(U0, S5[3], FY); fma2(U0, S5[6], FZ); // (2,1,1)
        ull U1 = mul2(S5[1], FX); fma2(U1, S5[4], FY); fma2(U1, S5[7], FZ);
        ull U2 = mul2(S5[2], FX); fma2(U2, S5[5], FY); fma2(U2, S5[8], FZ);

        #pragma unroll
        for (int oh = 0; oh < 2; oh++) {
            // duplicated (w,w) pairs straight from the constant port:
            // 12 x LDC.128 per (i,oh), zero dup movs.
            const ulonglong2* w = wdt + (i * 2 + oh) * 12;
            int o0 = 4 * oh;
            {   // combo 0 (A -> MS), combo 3 (B -> MS)
                ulonglong2 a01 = w[0],  a23 = w[1];
                ulonglong2 b01 = w[6],  b23 = w[7];
                ull wa[4] = {a01.x, a01.y, a23.x, a23.y};
                ull wb[4] = {b01.x, b01.y, b23.x, b23.y};
                #pragma unroll
                for (int r = 0; r < 4; r++) {
                    fma2(MS[o0 + r], wa[r], A);
                    fma2(MS[o0 + r], wb[r], B);
                }
            }
            {   // combo 1 (P -> MV), combo 2 (Q -> MV)
                ulonglong2 p01 = w[2],  p23 = w[3];
                ulonglong2 q01 = w[4],  q23 = w[5];
                ull wp[4] = {p01.x, p01.y, p23.x, p23.y};
                ull wq[4] = {q01.x, q01.y, q23.x, q23.y};
                #pragma unroll
                for (int r = 0; r < 4; r++) {
                    int o = o0 + r;
                    fma2(MV[o][0], wp[r], P0); fma2(MV[o][0], wq[r], Q0);
                    fma2(MV[o][1], wp[r], P1); fma2(MV[o][1], wq[r], Q1);
                    fma2(MV[o][2], wp[r], P2); fma2(MV[o][2], wq[r], Q2);
                }
            }
            {   // combo 4 (R -> MV), combo 5 (U -> MV)
                ulonglong2 r01 = w[8],  r23 = w[9];
                ulonglong2 u01 = w[10], u23 = w[11];
                ull wr[4] = {r01.x, r01.y, r23.x, r23.y};
                ull wu[4] = {u01.x, u01.y, u23.x, u23.y};
                #pragma unroll
                for (int r = 0; r < 4; r++) {
                    int o = o0 + r;
                    fma2(MV[o][0], wr[r], R0); fma2(MV[o][0], wu[r], U0);
                    fma2(MV[o][1], wr[r], R1); fma2(MV[o][1], wu[r], U1);
                    fma2(MV[o][2], wr[r], R2); fma2(MV[o][2], wu[r], U2);
                }
            }
        }
    }
    __syncwarp();   // interleaved staging reads complete before overwrite

    // ---- unpack msg rows into scatter staging (overlays union) ----
    float* bA = uni[warp];
    float* bB = uni[warp] + 32 * ROWF;
    {
        float* wA = bA + lane * ROWF;
        float* wB = bB + lane * ROWF;
        // msg layout: [0..7]=MS, [8+3o+k]=MV[o][k]
        #pragma unroll
        for (int jq = 0; jq < 8; jq++) {
            float4 a4, b4;
            #pragma unroll
            for (int t = 0; t < 4; t++) {
                int j = 4 * jq + t;
                ull m = (j < 8) ? MS[j] : MV[(j - 8) / 3][(j - 8) % 3];
                float2 f = upk2(m);
                (&a4.x)[t] = f.x;
                (&b4.x)[t] = f.y;
            }
            *reinterpret_cast<float4*>(wA + 4 * jq) = a4;
            *reinterpret_cast<float4*>(wB + 4 * jq) = b4;
        }
    }
    __syncwarp();

    // ---- cooperative coalesced scatter: 8 lanes per target row ----
    #pragma unroll
    for (int p = 0; p < 16; p++) {
        int row = (p & 7) * 4 + rsub;          // 0..31
        int er  = (p < 8) ? row : row + 32;    // edge offset within warp
        int tidx = __shfl_sync(FULL, (p < 8) ? ta : tb, row);
        const float* src = ((p < 8) ? bA : bB) + row * ROWF + piece * 4;
        float4 v = *reinterpret_cast<const float4*>(src);
        if (ebase + er < E) {
            float* dst = out + (size_t)tidx * 32 + piece * 4;
            asm volatile("red.global.add.v4.f32 [%0], {%1, %2, %3, %4};"
                         :: "l"(dst), "f"(v.x), "f"(v.y), "f"(v.z), "f"(v.w)
                         : "memory");
        }
    }
}

// ============================================================================
// Launch: dup kernel (k-folded, duplicated weights) -> D2D memcpyToSymbol ->
// memset output -> edge kernel. All graph-capturable, no allocations.
// ============================================================================
extern "C" void kernel_launch(void* const* d_in, const int* in_sizes, int n_in,
                              void* d_out, int out_size) {
    const float* node = (const float*)d_in[0];
    const int*   ei   = (const int*)  d_in[1];
    const float* sh0  = (const float*)d_in[2];
    const float* sh1  = (const float*)d_in[3];
    const float* sh2  = (const float*)d_in[4];
    const float* W    = (const float*)d_in[5];
    int E = in_sizes[1] / 2;

    CGParams P;
    float tmp[45];
    hostcg::h_so3(0, 0, 0, tmp); P.k[0] = tmp[0];
    hostcg::h_so3(0, 1, 1, tmp); P.k[1] = tmp[0];
    hostcg::h_so3(1, 0, 1, tmp); P.k[2] = tmp[0];
    hostcg::h_so3(1, 1, 0, tmp); P.k[3] = tmp[0];
    hostcg::h_so3(1, 1, 1, tmp); P.k[4] = tmp[5];
    P.k[5] = 1.0f;
    hostcg::h_so3(2, 1, 1, tmp);
    for (int x = 0; x < 45; x++) P.c5[x] = tmp[x];

    cudaMemsetAsync(d_out, 0, (size_t)out_size * sizeof(float), 0);
    dup_kernel<<<1, 384>>>(W, P);

    void* dupAddr = nullptr;
    cudaGetSymbolAddress(&dupAddr, g_Wdup);
    cudaMemcpyToSymbolAsync(cWd, dupAddr, 384 * sizeof(float2), 0,
                            cudaMemcpyDeviceToDevice, 0);

    int blocks = (E + 2 * TPB - 1) / (2 * TPB);
    edge_tp_kernel<<<blocks, TPB>>>(node, ei, sh0, sh1, sh2, (float*)d_out, E, P);
}